// round 2
// baseline (speedup 1.0000x reference)
#include <cuda_runtime.h>
#include <math.h>

// Problem constants (fixed by the dataset)
#define NT   16384       // tokens
#define DM   1024        // d_model
#define HS   1024        // h_seg
#define NSEG 4

// GEMM tiling
#define BM 128
#define BN 128
#define BK 8
#define KT1 (DM / BK)
#define KT2 (HS / BK)

#define MAX_ROWS (NT + NSEG * BM)   // 16896: each segment padded to BM multiple
#define MTILES   (MAX_ROWS / BM)    // 132

// ---------------- device scratch (static, allocation-free) ----------------
__device__ int   g_perm[MAX_ROWS];
__device__ int   g_count[NSEG];
__device__ int   g_cursor[NSEG];
__device__ int   g_off[NSEG + 1];
__device__ int   g_is32;                        // 1 if indices are int32, 0 if int64
__device__ float g_G[(size_t)MAX_ROWS * HS];    // gate out, then swiglu hidden (in place)
__device__ float g_U[(size_t)MAX_ROWS * HS];    // up out

// segment of token i under either dtype
__device__ __forceinline__ int seg_of(const int* __restrict__ idx32, int i) {
    return g_is32 ? idx32[i] : idx32[2 * i];    // int64 little-endian: low word
}

// ---------------- routing kernels ----------------
__global__ void k_prep() {
    int i = blockIdx.x * blockDim.x + threadIdx.x;
    if (i < MAX_ROWS) g_perm[i] = -1;
    if (i < NSEG) { g_count[i] = 0; g_cursor[i] = 0; }
    if (i == 0) g_is32 = 0;
}

// Probe dtype: odd 32-bit words of the first NT words are all zero iff int64.
__global__ void k_detect(const int* __restrict__ idx32) {
    int i = blockIdx.x * blockDim.x + threadIdx.x;   // i < NT/2
    if (i < NT / 2) {
        int v = idx32[2 * i + 1];
        if (v != 0 && (__ballot_sync(__activemask(), 1) ? 1 : 0)) {
            // only a handful of atomics in the int32 case; none in the int64 case
            atomicExch(&g_is32, 1);
        }
    }
}

__global__ void k_count(const int* __restrict__ idx32) {
    int i = blockIdx.x * blockDim.x + threadIdx.x;
    if (i < NT) {
        int s = seg_of(idx32, i);
        atomicAdd(&g_count[s & (NSEG - 1)], 1);
    }
}

__global__ void k_off() {
    if (threadIdx.x == 0 && blockIdx.x == 0) {
        int o = 0;
        for (int s = 0; s < NSEG; s++) {
            g_off[s] = o;
            o += ((g_count[s] + BM - 1) / BM) * BM;
        }
        g_off[NSEG] = o;
    }
}

__global__ void k_scatter(const int* __restrict__ idx32) {
    int i = blockIdx.x * blockDim.x + threadIdx.x;
    if (i < NT) {
        int s = seg_of(idx32, i) & (NSEG - 1);
        int pos = g_off[s] + atomicAdd(&g_cursor[s], 1);
        g_perm[pos] = i;
    }
}

// ---------------- GEMM 1: G = Xg @ gate_w[seg], U = Xg @ up_w[seg] ----------------
// A rows gathered through g_perm; B selected by segment of the M-tile.
__global__ __launch_bounds__(256, 2)
void gemm1(const float* __restrict__ x,
           const float* __restrict__ gate_w,
           const float* __restrict__ up_w)
{
    const int m0 = blockIdx.x * BM;
    if (m0 >= g_off[NSEG]) return;
    const int n0 = blockIdx.y * BN;

    int seg = 0;
#pragma unroll
    for (int s = 1; s < NSEG; s++) if (m0 >= g_off[s]) seg = s;

    const float* __restrict__ W = (blockIdx.z ? up_w : gate_w) + (size_t)seg * DM * HS;
    float* __restrict__ C = (blockIdx.z ? g_U : g_G);

    __shared__ float As[2][BK][BM];
    __shared__ float Bs[2][BK][BN];

    const int tid  = threadIdx.x;
    const int arow = tid >> 1;            // 0..127
    const int acol = (tid & 1) * 4;       // 0 or 4
    const int brow = tid >> 5;            // 0..7
    const int bcol = (tid & 31) * 4;      // 0..124
    const int tx = tid & 15, ty = tid >> 4;

    const int grow = g_perm[m0 + arow];
    const float* aptr = (grow >= 0) ? (x + (size_t)grow * DM) : nullptr;

    float acc[8][8];
#pragma unroll
    for (int i = 0; i < 8; i++)
#pragma unroll
        for (int j = 0; j < 8; j++) acc[i][j] = 0.f;

    // preload tile 0
    {
        float4 a4 = aptr ? *reinterpret_cast<const float4*>(aptr + acol)
                         : make_float4(0.f, 0.f, 0.f, 0.f);
        As[0][acol + 0][arow] = a4.x; As[0][acol + 1][arow] = a4.y;
        As[0][acol + 2][arow] = a4.z; As[0][acol + 3][arow] = a4.w;
        float4 b4 = *reinterpret_cast<const float4*>(W + (size_t)brow * HS + n0 + bcol);
        *reinterpret_cast<float4*>(&Bs[0][brow][bcol]) = b4;
    }
    __syncthreads();

    int cur = 0;
    for (int kt = 0; kt < KT1; kt++) {
        float4 a4, b4;
        const bool more = (kt + 1 < KT1);
        if (more) {
            const int k0 = (kt + 1) * BK;
            a4 = aptr ? *reinterpret_cast<const float4*>(aptr + k0 + acol)
                      : make_float4(0.f, 0.f, 0.f, 0.f);
            b4 = *reinterpret_cast<const float4*>(W + (size_t)(k0 + brow) * HS + n0 + bcol);
        }
#pragma unroll
        for (int k = 0; k < BK; k++) {
            float ra[8], rb[8];
            *reinterpret_cast<float4*>(ra)     = *reinterpret_cast<const float4*>(&As[cur][k][ty * 8]);
            *reinterpret_cast<float4*>(ra + 4) = *reinterpret_cast<const float4*>(&As[cur][k][ty * 8 + 4]);
            *reinterpret_cast<float4*>(rb)     = *reinterpret_cast<const float4*>(&Bs[cur][k][tx * 8]);
            *reinterpret_cast<float4*>(rb + 4) = *reinterpret_cast<const float4*>(&Bs[cur][k][tx * 8 + 4]);
#pragma unroll
            for (int i = 0; i < 8; i++)
#pragma unroll
                for (int j = 0; j < 8; j++)
                    acc[i][j] += ra[i] * rb[j];
        }
        if (more) {
            const int nxt = cur ^ 1;
            As[nxt][acol + 0][arow] = a4.x; As[nxt][acol + 1][arow] = a4.y;
            As[nxt][acol + 2][arow] = a4.z; As[nxt][acol + 3][arow] = a4.w;
            *reinterpret_cast<float4*>(&Bs[nxt][brow][bcol]) = b4;
            __syncthreads();
            cur = nxt;
        }
    }

#pragma unroll
    for (int i = 0; i < 8; i++) {
        const int row = m0 + ty * 8 + i;
        float* cp = C + (size_t)row * HS + n0 + tx * 8;
        *reinterpret_cast<float4*>(cp)     = make_float4(acc[i][0], acc[i][1], acc[i][2], acc[i][3]);
        *reinterpret_cast<float4*>(cp + 4) = make_float4(acc[i][4], acc[i][5], acc[i][6], acc[i][7]);
    }
}

// ---------------- SwiGLU elementwise: H = silu(G) * U (in place into g_G) ----------------
__global__ void k_swiglu() {
    size_t i = ((size_t)blockIdx.x * blockDim.x + threadIdx.x) * 4;
    if (i < (size_t)MAX_ROWS * HS) {
        float4 g4 = *reinterpret_cast<float4*>(&g_G[i]);
        float4 u4 = *reinterpret_cast<float4*>(&g_U[i]);
        g4.x = (g4.x / (1.f + __expf(-g4.x))) * u4.x;
        g4.y = (g4.y / (1.f + __expf(-g4.y))) * u4.y;
        g4.z = (g4.z / (1.f + __expf(-g4.z))) * u4.z;
        g4.w = (g4.w / (1.f + __expf(-g4.w))) * u4.w;
        *reinterpret_cast<float4*>(&g_G[i]) = g4;
    }
}

// ---------------- GEMM 2: out[token] = H @ down_w[seg], scatter by perm ----------------
__global__ __launch_bounds__(256, 2)
void gemm2(const float* __restrict__ down_w, float* __restrict__ out)
{
    const int m0 = blockIdx.x * BM;
    if (m0 >= g_off[NSEG]) return;
    const int n0 = blockIdx.y * BN;

    int seg = 0;
#pragma unroll
    for (int s = 1; s < NSEG; s++) if (m0 >= g_off[s]) seg = s;

    const float* __restrict__ W = down_w + (size_t)seg * HS * DM;
    const float* __restrict__ A = g_G;

    __shared__ float As[2][BK][BM];
    __shared__ float Bs[2][BK][BN];

    const int tid  = threadIdx.x;
    const int arow = tid >> 1;
    const int acol = (tid & 1) * 4;
    const int brow = tid >> 5;
    const int bcol = (tid & 31) * 4;
    const int tx = tid & 15, ty = tid >> 4;

    const float* aptr = A + (size_t)(m0 + arow) * HS;

    float acc[8][8];
#pragma unroll
    for (int i = 0; i < 8; i++)
#pragma unroll
        for (int j = 0; j < 8; j++) acc[i][j] = 0.f;

    {
        float4 a4 = *reinterpret_cast<const float4*>(aptr + acol);
        As[0][acol + 0][arow] = a4.x; As[0][acol + 1][arow] = a4.y;
        As[0][acol + 2][arow] = a4.z; As[0][acol + 3][arow] = a4.w;
        float4 b4 = *reinterpret_cast<const float4*>(W + (size_t)brow * DM + n0 + bcol);
        *reinterpret_cast<float4*>(&Bs[0][brow][bcol]) = b4;
    }
    __syncthreads();

    int cur = 0;
    for (int kt = 0; kt < KT2; kt++) {
        float4 a4, b4;
        const bool more = (kt + 1 < KT2);
        if (more) {
            const int k0 = (kt + 1) * BK;
            a4 = *reinterpret_cast<const float4*>(aptr + k0 + acol);
            b4 = *reinterpret_cast<const float4*>(W + (size_t)(k0 + brow) * DM + n0 + bcol);
        }
#pragma unroll
        for (int k = 0; k < BK; k++) {
            float ra[8], rb[8];
            *reinterpret_cast<float4*>(ra)     = *reinterpret_cast<const float4*>(&As[cur][k][ty * 8]);
            *reinterpret_cast<float4*>(ra + 4) = *reinterpret_cast<const float4*>(&As[cur][k][ty * 8 + 4]);
            *reinterpret_cast<float4*>(rb)     = *reinterpret_cast<const float4*>(&Bs[cur][k][tx * 8]);
            *reinterpret_cast<float4*>(rb + 4) = *reinterpret_cast<const float4*>(&Bs[cur][k][tx * 8 + 4]);
#pragma unroll
            for (int i = 0; i < 8; i++)
#pragma unroll
                for (int j = 0; j < 8; j++)
                    acc[i][j] += ra[i] * rb[j];
        }
        if (more) {
            const int nxt = cur ^ 1;
            As[nxt][acol + 0][arow] = a4.x; As[nxt][acol + 1][arow] = a4.y;
            As[nxt][acol + 2][arow] = a4.z; As[nxt][acol + 3][arow] = a4.w;
            *reinterpret_cast<float4*>(&Bs[nxt][brow][bcol]) = b4;
            __syncthreads();
            cur = nxt;
        }
    }

#pragma unroll
    for (int i = 0; i < 8; i++) {
        const int token = g_perm[m0 + ty * 8 + i];
        if (token >= 0) {
            float* cp = out + (size_t)token * DM + n0 + tx * 8;
            *reinterpret_cast<float4*>(cp)     = make_float4(acc[i][0], acc[i][1], acc[i][2], acc[i][3]);
            *reinterpret_cast<float4*>(cp + 4) = make_float4(acc[i][4], acc[i][5], acc[i][6], acc[i][7]);
        }
    }
}

// ---------------- entry point ----------------
extern "C" void kernel_launch(void* const* d_in, const int* in_sizes, int n_in,
                              void* d_out, int out_size)
{
    const float* x   = (const float*)d_in[0];
    const float* gw  = (const float*)d_in[1];
    const float* uw  = (const float*)d_in[2];
    const float* dw  = (const float*)d_in[3];
    const int*   idx = (const int*)d_in[4];
    float* out = (float*)d_out;

    k_prep<<<(MAX_ROWS + 255) / 256, 256>>>();
    k_detect<<<(NT / 2 + 255) / 256, 256>>>(idx);
    k_count<<<(NT + 255) / 256, 256>>>(idx);
    k_off<<<1, 32>>>();
    k_scatter<<<(NT + 255) / 256, 256>>>(idx);

    dim3 g1(MTILES, HS / BN, 2);
    gemm1<<<g1, 256>>>(x, gw, uw);

    size_t nelem = (size_t)MAX_ROWS * HS;
    k_swiglu<<<(unsigned)((nelem / 4 + 255) / 256), 256>>>();

    dim3 g2(MTILES, DM / BN, 1);
    gemm2<<<g2, 256>>>(dw, out);
}

// round 3
// speedup vs baseline: 1.0005x; 1.0005x over previous
#include <cuda_runtime.h>
#include <math.h>

// Problem constants (fixed by the dataset)
#define NT   16384       // tokens
#define DM   1024        // d_model
#define HS   1024        // h_seg
#define NSEG 4

// GEMM tiling
#define BM 128
#define BN 128
#define BK 8
#define KT1 (DM / BK)
#define KT2 (HS / BK)

#define MAX_ROWS (NT + NSEG * BM)   // 16896: each segment padded to BM multiple
#define MTILES   (MAX_ROWS / BM)    // 132

// ---------------- device scratch (static, allocation-free) ----------------
__device__ int   g_perm[MAX_ROWS];
__device__ int   g_count[NSEG];
__device__ int   g_cursor[NSEG];
__device__ int   g_off[NSEG + 1];
__device__ int   g_is32;                        // 1 if indices are int32, 0 if int64
__device__ float g_G[(size_t)MAX_ROWS * HS];    // gate out, then swiglu hidden (in place)
__device__ float g_U[(size_t)MAX_ROWS * HS];    // up out

// segment of token i under either dtype
__device__ __forceinline__ int seg_of(const int* __restrict__ idx32, int i) {
    return g_is32 ? idx32[i] : idx32[2 * i];    // int64 little-endian: low word
}

// ---------------- routing kernels ----------------
__global__ void k_prep() {
    int i = blockIdx.x * blockDim.x + threadIdx.x;
    if (i < MAX_ROWS) g_perm[i] = -1;
    if (i < NSEG) { g_count[i] = 0; g_cursor[i] = 0; }
    if (i == 0) g_is32 = 0;
}

// Probe dtype: odd 32-bit words of the first NT words are all zero iff int64.
__global__ void k_detect(const int* __restrict__ idx32) {
    int i = blockIdx.x * blockDim.x + threadIdx.x;   // i < NT/2
    if (i < NT / 2) {
        int v = idx32[2 * i + 1];
        if (v != 0 && (__ballot_sync(__activemask(), 1) ? 1 : 0)) {
            // only a handful of atomics in the int32 case; none in the int64 case
            atomicExch(&g_is32, 1);
        }
    }
}

__global__ void k_count(const int* __restrict__ idx32) {
    int i = blockIdx.x * blockDim.x + threadIdx.x;
    if (i < NT) {
        int s = seg_of(idx32, i);
        atomicAdd(&g_count[s & (NSEG - 1)], 1);
    }
}

__global__ void k_off() {
    if (threadIdx.x == 0 && blockIdx.x == 0) {
        int o = 0;
        for (int s = 0; s < NSEG; s++) {
            g_off[s] = o;
            o += ((g_count[s] + BM - 1) / BM) * BM;
        }
        g_off[NSEG] = o;
    }
}

__global__ void k_scatter(const int* __restrict__ idx32) {
    int i = blockIdx.x * blockDim.x + threadIdx.x;
    if (i < NT) {
        int s = seg_of(idx32, i) & (NSEG - 1);
        int pos = g_off[s] + atomicAdd(&g_cursor[s], 1);
        g_perm[pos] = i;
    }
}

// ---------------- GEMM 1: G = Xg @ gate_w[seg], U = Xg @ up_w[seg] ----------------
// A rows gathered through g_perm; B selected by segment of the M-tile.
__global__ __launch_bounds__(256, 2)
void gemm1(const float* __restrict__ x,
           const float* __restrict__ gate_w,
           const float* __restrict__ up_w)
{
    const int m0 = blockIdx.x * BM;
    if (m0 >= g_off[NSEG]) return;
    const int n0 = blockIdx.y * BN;

    int seg = 0;
#pragma unroll
    for (int s = 1; s < NSEG; s++) if (m0 >= g_off[s]) seg = s;

    const float* __restrict__ W = (blockIdx.z ? up_w : gate_w) + (size_t)seg * DM * HS;
    float* __restrict__ C = (blockIdx.z ? g_U : g_G);

    __shared__ float As[2][BK][BM];
    __shared__ float Bs[2][BK][BN];

    const int tid  = threadIdx.x;
    const int arow = tid >> 1;            // 0..127
    const int acol = (tid & 1) * 4;       // 0 or 4
    const int brow = tid >> 5;            // 0..7
    const int bcol = (tid & 31) * 4;      // 0..124
    const int tx = tid & 15, ty = tid >> 4;

    const int grow = g_perm[m0 + arow];
    const float* aptr = (grow >= 0) ? (x + (size_t)grow * DM) : nullptr;

    float acc[8][8];
#pragma unroll
    for (int i = 0; i < 8; i++)
#pragma unroll
        for (int j = 0; j < 8; j++) acc[i][j] = 0.f;

    // preload tile 0
    {
        float4 a4 = aptr ? *reinterpret_cast<const float4*>(aptr + acol)
                         : make_float4(0.f, 0.f, 0.f, 0.f);
        As[0][acol + 0][arow] = a4.x; As[0][acol + 1][arow] = a4.y;
        As[0][acol + 2][arow] = a4.z; As[0][acol + 3][arow] = a4.w;
        float4 b4 = *reinterpret_cast<const float4*>(W + (size_t)brow * HS + n0 + bcol);
        *reinterpret_cast<float4*>(&Bs[0][brow][bcol]) = b4;
    }
    __syncthreads();

    int cur = 0;
    for (int kt = 0; kt < KT1; kt++) {
        float4 a4, b4;
        const bool more = (kt + 1 < KT1);
        if (more) {
            const int k0 = (kt + 1) * BK;
            a4 = aptr ? *reinterpret_cast<const float4*>(aptr + k0 + acol)
                      : make_float4(0.f, 0.f, 0.f, 0.f);
            b4 = *reinterpret_cast<const float4*>(W + (size_t)(k0 + brow) * HS + n0 + bcol);
        }
#pragma unroll
        for (int k = 0; k < BK; k++) {
            float ra[8], rb[8];
            *reinterpret_cast<float4*>(ra)     = *reinterpret_cast<const float4*>(&As[cur][k][ty * 8]);
            *reinterpret_cast<float4*>(ra + 4) = *reinterpret_cast<const float4*>(&As[cur][k][ty * 8 + 4]);
            *reinterpret_cast<float4*>(rb)     = *reinterpret_cast<const float4*>(&Bs[cur][k][tx * 8]);
            *reinterpret_cast<float4*>(rb + 4) = *reinterpret_cast<const float4*>(&Bs[cur][k][tx * 8 + 4]);
#pragma unroll
            for (int i = 0; i < 8; i++)
#pragma unroll
                for (int j = 0; j < 8; j++)
                    acc[i][j] += ra[i] * rb[j];
        }
        if (more) {
            const int nxt = cur ^ 1;
            As[nxt][acol + 0][arow] = a4.x; As[nxt][acol + 1][arow] = a4.y;
            As[nxt][acol + 2][arow] = a4.z; As[nxt][acol + 3][arow] = a4.w;
            *reinterpret_cast<float4*>(&Bs[nxt][brow][bcol]) = b4;
            __syncthreads();
            cur = nxt;
        }
    }

#pragma unroll
    for (int i = 0; i < 8; i++) {
        const int row = m0 + ty * 8 + i;
        float* cp = C + (size_t)row * HS + n0 + tx * 8;
        *reinterpret_cast<float4*>(cp)     = make_float4(acc[i][0], acc[i][1], acc[i][2], acc[i][3]);
        *reinterpret_cast<float4*>(cp + 4) = make_float4(acc[i][4], acc[i][5], acc[i][6], acc[i][7]);
    }
}

// ---------------- SwiGLU elementwise: H = silu(G) * U (in place into g_G) ----------------
__global__ void k_swiglu() {
    size_t i = ((size_t)blockIdx.x * blockDim.x + threadIdx.x) * 4;
    if (i < (size_t)MAX_ROWS * HS) {
        float4 g4 = *reinterpret_cast<float4*>(&g_G[i]);
        float4 u4 = *reinterpret_cast<float4*>(&g_U[i]);
        g4.x = (g4.x / (1.f + __expf(-g4.x))) * u4.x;
        g4.y = (g4.y / (1.f + __expf(-g4.y))) * u4.y;
        g4.z = (g4.z / (1.f + __expf(-g4.z))) * u4.z;
        g4.w = (g4.w / (1.f + __expf(-g4.w))) * u4.w;
        *reinterpret_cast<float4*>(&g_G[i]) = g4;
    }
}

// ---------------- GEMM 2: out[token] = H @ down_w[seg], scatter by perm ----------------
__global__ __launch_bounds__(256, 2)
void gemm2(const float* __restrict__ down_w, float* __restrict__ out)
{
    const int m0 = blockIdx.x * BM;
    if (m0 >= g_off[NSEG]) return;
    const int n0 = blockIdx.y * BN;

    int seg = 0;
#pragma unroll
    for (int s = 1; s < NSEG; s++) if (m0 >= g_off[s]) seg = s;

    const float* __restrict__ W = down_w + (size_t)seg * HS * DM;
    const float* __restrict__ A = g_G;

    __shared__ float As[2][BK][BM];
    __shared__ float Bs[2][BK][BN];

    const int tid  = threadIdx.x;
    const int arow = tid >> 1;
    const int acol = (tid & 1) * 4;
    const int brow = tid >> 5;
    const int bcol = (tid & 31) * 4;
    const int tx = tid & 15, ty = tid >> 4;

    const float* aptr = A + (size_t)(m0 + arow) * HS;

    float acc[8][8];
#pragma unroll
    for (int i = 0; i < 8; i++)
#pragma unroll
        for (int j = 0; j < 8; j++) acc[i][j] = 0.f;

    {
        float4 a4 = *reinterpret_cast<const float4*>(aptr + acol);
        As[0][acol + 0][arow] = a4.x; As[0][acol + 1][arow] = a4.y;
        As[0][acol + 2][arow] = a4.z; As[0][acol + 3][arow] = a4.w;
        float4 b4 = *reinterpret_cast<const float4*>(W + (size_t)brow * DM + n0 + bcol);
        *reinterpret_cast<float4*>(&Bs[0][brow][bcol]) = b4;
    }
    __syncthreads();

    int cur = 0;
    for (int kt = 0; kt < KT2; kt++) {
        float4 a4, b4;
        const bool more = (kt + 1 < KT2);
        if (more) {
            const int k0 = (kt + 1) * BK;
            a4 = *reinterpret_cast<const float4*>(aptr + k0 + acol);
            b4 = *reinterpret_cast<const float4*>(W + (size_t)(k0 + brow) * DM + n0 + bcol);
        }
#pragma unroll
        for (int k = 0; k < BK; k++) {
            float ra[8], rb[8];
            *reinterpret_cast<float4*>(ra)     = *reinterpret_cast<const float4*>(&As[cur][k][ty * 8]);
            *reinterpret_cast<float4*>(ra + 4) = *reinterpret_cast<const float4*>(&As[cur][k][ty * 8 + 4]);
            *reinterpret_cast<float4*>(rb)     = *reinterpret_cast<const float4*>(&Bs[cur][k][tx * 8]);
            *reinterpret_cast<float4*>(rb + 4) = *reinterpret_cast<const float4*>(&Bs[cur][k][tx * 8 + 4]);
#pragma unroll
            for (int i = 0; i < 8; i++)
#pragma unroll
                for (int j = 0; j < 8; j++)
                    acc[i][j] += ra[i] * rb[j];
        }
        if (more) {
            const int nxt = cur ^ 1;
            As[nxt][acol + 0][arow] = a4.x; As[nxt][acol + 1][arow] = a4.y;
            As[nxt][acol + 2][arow] = a4.z; As[nxt][acol + 3][arow] = a4.w;
            *reinterpret_cast<float4*>(&Bs[nxt][brow][bcol]) = b4;
            __syncthreads();
            cur = nxt;
        }
    }

#pragma unroll
    for (int i = 0; i < 8; i++) {
        const int token = g_perm[m0 + ty * 8 + i];
        if (token >= 0) {
            float* cp = out + (size_t)token * DM + n0 + tx * 8;
            *reinterpret_cast<float4*>(cp)     = make_float4(acc[i][0], acc[i][1], acc[i][2], acc[i][3]);
            *reinterpret_cast<float4*>(cp + 4) = make_float4(acc[i][4], acc[i][5], acc[i][6], acc[i][7]);
        }
    }
}

// ---------------- entry point ----------------
extern "C" void kernel_launch(void* const* d_in, const int* in_sizes, int n_in,
                              void* d_out, int out_size)
{
    const float* x   = (const float*)d_in[0];
    const float* gw  = (const float*)d_in[1];
    const float* uw  = (const float*)d_in[2];
    const float* dw  = (const float*)d_in[3];
    const int*   idx = (const int*)d_in[4];
    float* out = (float*)d_out;

    k_prep<<<(MAX_ROWS + 255) / 256, 256>>>();
    k_detect<<<(NT / 2 + 255) / 256, 256>>>(idx);
    k_count<<<(NT + 255) / 256, 256>>>(idx);
    k_off<<<1, 32>>>();
    k_scatter<<<(NT + 255) / 256, 256>>>(idx);

    dim3 g1(MTILES, HS / BN, 2);
    gemm1<<<g1, 256>>>(x, gw, uw);

    size_t nelem = (size_t)MAX_ROWS * HS;
    k_swiglu<<<(unsigned)((nelem / 4 + 255) / 256), 256>>>();

    dim3 g2(MTILES, DM / BN, 1);
    gemm2<<<g2, 256>>>(dw, out);
}

// round 4
// speedup vs baseline: 1.0006x; 1.0001x over previous
#include <cuda_runtime.h>
#include <math.h>

// Problem constants (fixed by the dataset)
#define NT   16384       // tokens
#define DM   1024        // d_model
#define HS   1024        // h_seg
#define NSEG 4

// GEMM tiling
#define BM 128
#define BN 128
#define BK 8
#define KT1 (DM / BK)
#define KT2 (HS / BK)

#define MAX_ROWS (NT + NSEG * BM)   // 16896: each segment padded to BM multiple
#define MTILES   (MAX_ROWS / BM)    // 132

// ---------------- device scratch (static, allocation-free) ----------------
__device__ int   g_perm[MAX_ROWS];
__device__ int   g_count[NSEG];
__device__ int   g_cursor[NSEG];
__device__ int   g_off[NSEG + 1];
__device__ int   g_is32;                        // 1 if indices are int32, 0 if int64
__device__ float g_G[(size_t)MAX_ROWS * HS];    // gate out, then swiglu hidden (in place)
__device__ float g_U[(size_t)MAX_ROWS * HS];    // up out

// segment of token i under either dtype
__device__ __forceinline__ int seg_of(const int* __restrict__ idx32, int i) {
    return g_is32 ? idx32[i] : idx32[2 * i];    // int64 little-endian: low word
}

// ---------------- routing kernels ----------------
__global__ void k_prep() {
    int i = blockIdx.x * blockDim.x + threadIdx.x;
    if (i < MAX_ROWS) g_perm[i] = -1;
    if (i < NSEG) { g_count[i] = 0; g_cursor[i] = 0; }
    if (i == 0) g_is32 = 0;
}

// Probe dtype: odd 32-bit words of the first NT words are all zero iff int64.
__global__ void k_detect(const int* __restrict__ idx32) {
    int i = blockIdx.x * blockDim.x + threadIdx.x;   // i < NT/2
    if (i < NT / 2) {
        int v = idx32[2 * i + 1];
        if (v != 0 && (__ballot_sync(__activemask(), 1) ? 1 : 0)) {
            // only a handful of atomics in the int32 case; none in the int64 case
            atomicExch(&g_is32, 1);
        }
    }
}

__global__ void k_count(const int* __restrict__ idx32) {
    int i = blockIdx.x * blockDim.x + threadIdx.x;
    if (i < NT) {
        int s = seg_of(idx32, i);
        atomicAdd(&g_count[s & (NSEG - 1)], 1);
    }
}

__global__ void k_off() {
    if (threadIdx.x == 0 && blockIdx.x == 0) {
        int o = 0;
        for (int s = 0; s < NSEG; s++) {
            g_off[s] = o;
            o += ((g_count[s] + BM - 1) / BM) * BM;
        }
        g_off[NSEG] = o;
    }
}

__global__ void k_scatter(const int* __restrict__ idx32) {
    int i = blockIdx.x * blockDim.x + threadIdx.x;
    if (i < NT) {
        int s = seg_of(idx32, i) & (NSEG - 1);
        int pos = g_off[s] + atomicAdd(&g_cursor[s], 1);
        g_perm[pos] = i;
    }
}

// ---------------- GEMM 1: G = Xg @ gate_w[seg], U = Xg @ up_w[seg] ----------------
// A rows gathered through g_perm; B selected by segment of the M-tile.
__global__ __launch_bounds__(256, 2)
void gemm1(const float* __restrict__ x,
           const float* __restrict__ gate_w,
           const float* __restrict__ up_w)
{
    const int m0 = blockIdx.x * BM;
    if (m0 >= g_off[NSEG]) return;
    const int n0 = blockIdx.y * BN;

    int seg = 0;
#pragma unroll
    for (int s = 1; s < NSEG; s++) if (m0 >= g_off[s]) seg = s;

    const float* __restrict__ W = (blockIdx.z ? up_w : gate_w) + (size_t)seg * DM * HS;
    float* __restrict__ C = (blockIdx.z ? g_U : g_G);

    __shared__ float As[2][BK][BM];
    __shared__ float Bs[2][BK][BN];

    const int tid  = threadIdx.x;
    const int arow = tid >> 1;            // 0..127
    const int acol = (tid & 1) * 4;       // 0 or 4
    const int brow = tid >> 5;            // 0..7
    const int bcol = (tid & 31) * 4;      // 0..124
    const int tx = tid & 15, ty = tid >> 4;

    const int grow = g_perm[m0 + arow];
    const float* aptr = (grow >= 0) ? (x + (size_t)grow * DM) : nullptr;

    float acc[8][8];
#pragma unroll
    for (int i = 0; i < 8; i++)
#pragma unroll
        for (int j = 0; j < 8; j++) acc[i][j] = 0.f;

    // preload tile 0
    {
        float4 a4 = aptr ? *reinterpret_cast<const float4*>(aptr + acol)
                         : make_float4(0.f, 0.f, 0.f, 0.f);
        As[0][acol + 0][arow] = a4.x; As[0][acol + 1][arow] = a4.y;
        As[0][acol + 2][arow] = a4.z; As[0][acol + 3][arow] = a4.w;
        float4 b4 = *reinterpret_cast<const float4*>(W + (size_t)brow * HS + n0 + bcol);
        *reinterpret_cast<float4*>(&Bs[0][brow][bcol]) = b4;
    }
    __syncthreads();

    int cur = 0;
    for (int kt = 0; kt < KT1; kt++) {
        float4 a4, b4;
        const bool more = (kt + 1 < KT1);
        if (more) {
            const int k0 = (kt + 1) * BK;
            a4 = aptr ? *reinterpret_cast<const float4*>(aptr + k0 + acol)
                      : make_float4(0.f, 0.f, 0.f, 0.f);
            b4 = *reinterpret_cast<const float4*>(W + (size_t)(k0 + brow) * HS + n0 + bcol);
        }
#pragma unroll
        for (int k = 0; k < BK; k++) {
            float ra[8], rb[8];
            *reinterpret_cast<float4*>(ra)     = *reinterpret_cast<const float4*>(&As[cur][k][ty * 8]);
            *reinterpret_cast<float4*>(ra + 4) = *reinterpret_cast<const float4*>(&As[cur][k][ty * 8 + 4]);
            *reinterpret_cast<float4*>(rb)     = *reinterpret_cast<const float4*>(&Bs[cur][k][tx * 8]);
            *reinterpret_cast<float4*>(rb + 4) = *reinterpret_cast<const float4*>(&Bs[cur][k][tx * 8 + 4]);
#pragma unroll
            for (int i = 0; i < 8; i++)
#pragma unroll
                for (int j = 0; j < 8; j++)
                    acc[i][j] += ra[i] * rb[j];
        }
        if (more) {
            const int nxt = cur ^ 1;
            As[nxt][acol + 0][arow] = a4.x; As[nxt][acol + 1][arow] = a4.y;
            As[nxt][acol + 2][arow] = a4.z; As[nxt][acol + 3][arow] = a4.w;
            *reinterpret_cast<float4*>(&Bs[nxt][brow][bcol]) = b4;
            __syncthreads();
            cur = nxt;
        }
    }

#pragma unroll
    for (int i = 0; i < 8; i++) {
        const int row = m0 + ty * 8 + i;
        float* cp = C + (size_t)row * HS + n0 + tx * 8;
        *reinterpret_cast<float4*>(cp)     = make_float4(acc[i][0], acc[i][1], acc[i][2], acc[i][3]);
        *reinterpret_cast<float4*>(cp + 4) = make_float4(acc[i][4], acc[i][5], acc[i][6], acc[i][7]);
    }
}

// ---------------- SwiGLU elementwise: H = silu(G) * U (in place into g_G) ----------------
__global__ void k_swiglu() {
    size_t i = ((size_t)blockIdx.x * blockDim.x + threadIdx.x) * 4;
    if (i < (size_t)MAX_ROWS * HS) {
        float4 g4 = *reinterpret_cast<float4*>(&g_G[i]);
        float4 u4 = *reinterpret_cast<float4*>(&g_U[i]);
        g4.x = (g4.x / (1.f + __expf(-g4.x))) * u4.x;
        g4.y = (g4.y / (1.f + __expf(-g4.y))) * u4.y;
        g4.z = (g4.z / (1.f + __expf(-g4.z))) * u4.z;
        g4.w = (g4.w / (1.f + __expf(-g4.w))) * u4.w;
        *reinterpret_cast<float4*>(&g_G[i]) = g4;
    }
}

// ---------------- GEMM 2: out[token] = H @ down_w[seg], scatter by perm ----------------
__global__ __launch_bounds__(256, 2)
void gemm2(const float* __restrict__ down_w, float* __restrict__ out)
{
    const int m0 = blockIdx.x * BM;
    if (m0 >= g_off[NSEG]) return;
    const int n0 = blockIdx.y * BN;

    int seg = 0;
#pragma unroll
    for (int s = 1; s < NSEG; s++) if (m0 >= g_off[s]) seg = s;

    const float* __restrict__ W = down_w + (size_t)seg * HS * DM;
    const float* __restrict__ A = g_G;

    __shared__ float As[2][BK][BM];
    __shared__ float Bs[2][BK][BN];

    const int tid  = threadIdx.x;
    const int arow = tid >> 1;
    const int acol = (tid & 1) * 4;
    const int brow = tid >> 5;
    const int bcol = (tid & 31) * 4;
    const int tx = tid & 15, ty = tid >> 4;

    const float* aptr = A + (size_t)(m0 + arow) * HS;

    float acc[8][8];
#pragma unroll
    for (int i = 0; i < 8; i++)
#pragma unroll
        for (int j = 0; j < 8; j++) acc[i][j] = 0.f;

    {
        float4 a4 = *reinterpret_cast<const float4*>(aptr + acol);
        As[0][acol + 0][arow] = a4.x; As[0][acol + 1][arow] = a4.y;
        As[0][acol + 2][arow] = a4.z; As[0][acol + 3][arow] = a4.w;
        float4 b4 = *reinterpret_cast<const float4*>(W + (size_t)brow * DM + n0 + bcol);
        *reinterpret_cast<float4*>(&Bs[0][brow][bcol]) = b4;
    }
    __syncthreads();

    int cur = 0;
    for (int kt = 0; kt < KT2; kt++) {
        float4 a4, b4;
        const bool more = (kt + 1 < KT2);
        if (more) {
            const int k0 = (kt + 1) * BK;
            a4 = *reinterpret_cast<const float4*>(aptr + k0 + acol);
            b4 = *reinterpret_cast<const float4*>(W + (size_t)(k0 + brow) * DM + n0 + bcol);
        }
#pragma unroll
        for (int k = 0; k < BK; k++) {
            float ra[8], rb[8];
            *reinterpret_cast<float4*>(ra)     = *reinterpret_cast<const float4*>(&As[cur][k][ty * 8]);
            *reinterpret_cast<float4*>(ra + 4) = *reinterpret_cast<const float4*>(&As[cur][k][ty * 8 + 4]);
            *reinterpret_cast<float4*>(rb)     = *reinterpret_cast<const float4*>(&Bs[cur][k][tx * 8]);
            *reinterpret_cast<float4*>(rb + 4) = *reinterpret_cast<const float4*>(&Bs[cur][k][tx * 8 + 4]);
#pragma unroll
            for (int i = 0; i < 8; i++)
#pragma unroll
                for (int j = 0; j < 8; j++)
                    acc[i][j] += ra[i] * rb[j];
        }
        if (more) {
            const int nxt = cur ^ 1;
            As[nxt][acol + 0][arow] = a4.x; As[nxt][acol + 1][arow] = a4.y;
            As[nxt][acol + 2][arow] = a4.z; As[nxt][acol + 3][arow] = a4.w;
            *reinterpret_cast<float4*>(&Bs[nxt][brow][bcol]) = b4;
            __syncthreads();
            cur = nxt;
        }
    }

#pragma unroll
    for (int i = 0; i < 8; i++) {
        const int token = g_perm[m0 + ty * 8 + i];
        if (token >= 0) {
            float* cp = out + (size_t)token * DM + n0 + tx * 8;
            *reinterpret_cast<float4*>(cp)     = make_float4(acc[i][0], acc[i][1], acc[i][2], acc[i][3]);
            *reinterpret_cast<float4*>(cp + 4) = make_float4(acc[i][4], acc[i][5], acc[i][6], acc[i][7]);
        }
    }
}

// ---------------- entry point ----------------
extern "C" void kernel_launch(void* const* d_in, const int* in_sizes, int n_in,
                              void* d_out, int out_size)
{
    const float* x   = (const float*)d_in[0];
    const float* gw  = (const float*)d_in[1];
    const float* uw  = (const float*)d_in[2];
    const float* dw  = (const float*)d_in[3];
    const int*   idx = (const int*)d_in[4];
    float* out = (float*)d_out;

    k_prep<<<(MAX_ROWS + 255) / 256, 256>>>();
    k_detect<<<(NT / 2 + 255) / 256, 256>>>(idx);
    k_count<<<(NT + 255) / 256, 256>>>(idx);
    k_off<<<1, 32>>>();
    k_scatter<<<(NT + 255) / 256, 256>>>(idx);

    dim3 g1(MTILES, HS / BN, 2);
    gemm1<<<g1, 256>>>(x, gw, uw);

    size_t nelem = (size_t)MAX_ROWS * HS;
    k_swiglu<<<(unsigned)((nelem / 4 + 255) / 256), 256>>>();

    dim3 g2(MTILES, DM / BN, 1);
    gemm2<<<g2, 256>>>(dw, out);
}

// round 6
// speedup vs baseline: 2.2427x; 2.2414x over previous
#include <cuda_runtime.h>
#include <cuda_bf16.h>
#include <math.h>
#include <stdint.h>

// ---------------- problem constants ----------------
#define NT   16384
#define DM   1024
#define HS   1024
#define NSEG 4

#define BM   128
#define BN   128
#define BK   32
#define NKIT (1024 / BK)        // 32 k-iterations

#define MAX_ROWS (NT + NSEG * BM)   // 16896
#define MTILES   (MAX_ROWS / BM)    // 132

// SMEM: per stage 4 operand tiles (Ah, Al, Bh, Bl), each 128 rows x 32 bf16,
// row padded 64B->80B (conflict-free ldmatrix: bank step 20 mod 32).
#define ROWB     80
#define TILEB    (128 * ROWB)       // 10240
#define STAGEB   (4 * TILEB)        // 40960
#define NSTAGE   3
#define SMEM_G   (NSTAGE * STAGEB)  // 122880

// ---------------- device scratch ----------------
__device__ int g_perm[MAX_ROWS];
__device__ int g_count[NSEG];
__device__ int g_cursor[NSEG];
__device__ int g_off[NSEG + 1];
__device__ int g_is32;

__device__ __nv_bfloat16 g_xhi[(size_t)MAX_ROWS * DM];
__device__ __nv_bfloat16 g_xlo[(size_t)MAX_ROWS * DM];
__device__ float         g_G[(size_t)MAX_ROWS * HS];
__device__ float         g_U[(size_t)MAX_ROWS * HS];
__device__ __nv_bfloat16 g_hhi[(size_t)MAX_ROWS * HS];
__device__ __nv_bfloat16 g_hlo[(size_t)MAX_ROWS * HS];
// weights K-major [seg][n][k], split hi/lo
__device__ __nv_bfloat16 g_wghi[(size_t)NSEG * HS * DM];
__device__ __nv_bfloat16 g_wglo[(size_t)NSEG * HS * DM];
__device__ __nv_bfloat16 g_wuhi[(size_t)NSEG * HS * DM];
__device__ __nv_bfloat16 g_wulo[(size_t)NSEG * HS * DM];
__device__ __nv_bfloat16 g_wdhi[(size_t)NSEG * DM * HS];
__device__ __nv_bfloat16 g_wdlo[(size_t)NSEG * DM * HS];

// ---------------- small helpers ----------------
__device__ __forceinline__ uint32_t s2u(const void* p) {
    return (uint32_t)__cvta_generic_to_shared(p);
}
__device__ __forceinline__ void cpa16(uint32_t dst, const void* src) {
    asm volatile("cp.async.cg.shared.global [%0], [%1], 16;" :: "r"(dst), "l"(src));
}
#define CP_COMMIT() asm volatile("cp.async.commit_group;" ::: "memory")
#define CP_WAIT1()  asm volatile("cp.async.wait_group 1;" ::: "memory")
#define CP_WAIT0()  asm volatile("cp.async.wait_group 0;" ::: "memory")

__device__ __forceinline__ void ldmx4(uint32_t* r, uint32_t addr) {
    asm volatile("ldmatrix.sync.aligned.m8n8.x4.shared.b16 {%0,%1,%2,%3}, [%4];"
        : "=r"(r[0]), "=r"(r[1]), "=r"(r[2]), "=r"(r[3]) : "r"(addr));
}
__device__ __forceinline__ void mma16816(float* c, const uint32_t* a, const uint32_t* b) {
    asm volatile(
        "mma.sync.aligned.m16n8k16.row.col.f32.bf16.bf16.f32 "
        "{%0,%1,%2,%3}, {%4,%5,%6,%7}, {%8,%9}, {%0,%1,%2,%3};"
        : "+f"(c[0]), "+f"(c[1]), "+f"(c[2]), "+f"(c[3])
        : "r"(a[0]), "r"(a[1]), "r"(a[2]), "r"(a[3]), "r"(b[0]), "r"(b[1]));
}

__device__ __forceinline__ void split2(float v, __nv_bfloat16& h, __nv_bfloat16& l) {
    h = __float2bfloat16(v);
    l = __float2bfloat16(v - __bfloat162float(h));
}
__device__ __forceinline__ uint32_t pack2(__nv_bfloat16 a, __nv_bfloat16 b) {
    return ((uint32_t)__bfloat16_as_ushort(b) << 16) | __bfloat16_as_ushort(a);
}

// ---------------- routing kernels ----------------
__global__ void k_prep() {
    int i = blockIdx.x * blockDim.x + threadIdx.x;
    if (i < MAX_ROWS) g_perm[i] = -1;
    if (i < NSEG) { g_count[i] = 0; g_cursor[i] = 0; }
    if (i == 0) g_is32 = 0;
}
__global__ void k_detect(const int* __restrict__ idx32) {
    int i = blockIdx.x * blockDim.x + threadIdx.x;
    if (i < NT / 2) {
        if (idx32[2 * i + 1] != 0) atomicExch(&g_is32, 1);
    }
}
__device__ __forceinline__ int seg_of(const int* __restrict__ idx32, int i) {
    return (g_is32 ? idx32[i] : idx32[2 * i]) & (NSEG - 1);
}
__global__ void k_count(const int* __restrict__ idx32) {
    int i = blockIdx.x * blockDim.x + threadIdx.x;
    if (i < NT) atomicAdd(&g_count[seg_of(idx32, i)], 1);
}
__global__ void k_off() {
    if (threadIdx.x == 0 && blockIdx.x == 0) {
        int o = 0;
        for (int s = 0; s < NSEG; s++) {
            g_off[s] = o;
            o += ((g_count[s] + BM - 1) / BM) * BM;
        }
        g_off[NSEG] = o;
    }
}
__global__ void k_scatter(const int* __restrict__ idx32) {
    int i = blockIdx.x * blockDim.x + threadIdx.x;
    if (i < NT) {
        int s = seg_of(idx32, i);
        g_perm[g_off[s] + atomicAdd(&g_cursor[s], 1)] = i;
    }
}

// ---------------- conversion: gathered x -> bf16 hi/lo ----------------
__global__ void k_convx(const float* __restrict__ x) {
    int gid = blockIdx.x * blockDim.x + threadIdx.x;
    if (gid >= MAX_ROWS * (DM / 4)) return;
    int r = gid >> 8;
    int c = (gid & 255) << 2;
    int t = g_perm[r];
    float4 v = (t >= 0) ? *reinterpret_cast<const float4*>(x + (size_t)t * DM + c)
                        : make_float4(0.f, 0.f, 0.f, 0.f);
    __nv_bfloat16 hx, lx, hy, ly, hz, lz, hw, lw;
    split2(v.x, hx, lx); split2(v.y, hy, ly);
    split2(v.z, hz, lz); split2(v.w, hw, lw);
    size_t o = (size_t)r * DM + c;
    *reinterpret_cast<uint2*>(g_xhi + o) = make_uint2(pack2(hx, hy), pack2(hz, hw));
    *reinterpret_cast<uint2*>(g_xlo + o) = make_uint2(pack2(lx, ly), pack2(lz, lw));
}

// ---------------- conversion: weights fp32 [k][n] -> bf16 hi/lo [n][k] ----------------
__global__ void k_convw(const float* __restrict__ gw, const float* __restrict__ uw,
                        const float* __restrict__ dw) {
    __shared__ float tile[32][33];
    int mat = blockIdx.z >> 2, seg = blockIdx.z & 3;
    const float* W = (mat == 0 ? gw : (mat == 1 ? uw : dw)) + (size_t)seg * DM * HS;
    __nv_bfloat16* Ohi = (mat == 0 ? g_wghi : (mat == 1 ? g_wuhi : g_wdhi)) + (size_t)seg * DM * HS;
    __nv_bfloat16* Olo = (mat == 0 ? g_wglo : (mat == 1 ? g_wulo : g_wdlo)) + (size_t)seg * DM * HS;
    int n0 = blockIdx.x * 32, k0 = blockIdx.y * 32;
    int tx = threadIdx.x, ty = threadIdx.y;
#pragma unroll
    for (int i = 0; i < 4; i++)
        tile[ty + 8 * i][tx] = W[(size_t)(k0 + ty + 8 * i) * 1024 + n0 + tx];
    __syncthreads();
#pragma unroll
    for (int i = 0; i < 4; i++) {
        float v = tile[tx][ty + 8 * i];
        __nv_bfloat16 h, l; split2(v, h, l);
        size_t o = (size_t)(n0 + ty + 8 * i) * 1024 + k0 + tx;
        Ohi[o] = h; Olo[o] = l;
    }
}

// ---------------- stage loader ----------------
// one operand tile: 128 rows x 32 bf16 (64B) -> smem rows of 80B; 512 16B chunks
__device__ __forceinline__ void ld_tile(uint32_t sdst, const __nv_bfloat16* g, int tid) {
#pragma unroll
    for (int q = 0; q < 2; q++) {
        int id = q * 256 + tid;
        int row = id >> 2, c = id & 3;
        cpa16(sdst + row * ROWB + c * 16, g + (size_t)row * 1024 + c * 8);
    }
}
__device__ __forceinline__ void ld_stage(uint32_t sb,
                                         const __nv_bfloat16* gAh, const __nv_bfloat16* gAl,
                                         const __nv_bfloat16* gBh, const __nv_bfloat16* gBl,
                                         int kc, int tid) {
    int ko = kc * BK;
    ld_tile(sb,             gAh + ko, tid);
    ld_tile(sb + TILEB,     gAl + ko, tid);
    ld_tile(sb + 2 * TILEB, gBh + ko, tid);
    ld_tile(sb + 3 * TILEB, gBl + ko, tid);
}

// ---------------- GEMM mainloop (shared by both kernels) ----------------
// acc[2][8][4]: warp tile 32(M) x 64(N), m16n8k16 fragments, 3-product emulation.
__device__ __forceinline__ void gemm_mainloop(uint32_t smem_base,
                                              const __nv_bfloat16* gAh, const __nv_bfloat16* gAl,
                                              const __nv_bfloat16* gBh, const __nv_bfloat16* gBl,
                                              int tid, float acc[2][8][4]) {
    const int lane = tid & 31, wid = tid >> 5;
    const int wm = wid & 3, wn = wid >> 2;

#pragma unroll
    for (int i = 0; i < 2; i++)
#pragma unroll
        for (int j = 0; j < 8; j++)
#pragma unroll
            for (int q = 0; q < 4; q++) acc[i][j][q] = 0.f;

    ld_stage(smem_base,          gAh, gAl, gBh, gBl, 0, tid); CP_COMMIT();
    ld_stage(smem_base + STAGEB, gAh, gAl, gBh, gBl, 1, tid); CP_COMMIT();

    // per-lane ldmatrix address components (byte offsets within a tile)
    const int a_row = wm * 32 + (lane & 15);            // + mt*16
    const int a_kb  = (lane >> 4) << 4;                 // + ks*32
    const int b_row = wn * 64 + ((lane >> 4) << 3) + (lane & 7);   // + p*16
    const int b_kb  = ((lane >> 3) & 1) << 4;           // + ks*32

    for (int it = 0; it < NKIT; it++) {
        if (it + 2 < NKIT) CP_WAIT1(); else CP_WAIT0();
        __syncthreads();
        if (it + 2 < NKIT) {
            ld_stage(smem_base + ((it + 2) % NSTAGE) * STAGEB, gAh, gAl, gBh, gBl, it + 2, tid);
            CP_COMMIT();
        }
        const uint32_t sb = smem_base + (it % NSTAGE) * STAGEB;
#pragma unroll
        for (int ks = 0; ks < 2; ks++) {
            uint32_t aH[2][4], aL[2][4], bH[8][2], bL[8][2];
#pragma unroll
            for (int mt = 0; mt < 2; mt++) {
                uint32_t ad = sb + (a_row + mt * 16) * ROWB + ks * 32 + a_kb;
                ldmx4(aH[mt], ad);
                ldmx4(aL[mt], ad + TILEB);
            }
#pragma unroll
            for (int p = 0; p < 4; p++) {
                uint32_t bd = sb + 2 * TILEB + (b_row + p * 16) * ROWB + ks * 32 + b_kb;
                uint32_t r[4];
                ldmx4(r, bd);
                bH[2 * p][0] = r[0]; bH[2 * p][1] = r[1];
                bH[2 * p + 1][0] = r[2]; bH[2 * p + 1][1] = r[3];
                ldmx4(r, bd + TILEB);
                bL[2 * p][0] = r[0]; bL[2 * p][1] = r[1];
                bL[2 * p + 1][0] = r[2]; bL[2 * p + 1][1] = r[3];
            }
#pragma unroll
            for (int mt = 0; mt < 2; mt++)
#pragma unroll
                for (int nt = 0; nt < 8; nt++) {
                    mma16816(acc[mt][nt], aH[mt], bH[nt]);
                    mma16816(acc[mt][nt], aH[mt], bL[nt]);
                    mma16816(acc[mt][nt], aL[mt], bH[nt]);
                }
        }
    }
}

// ---------------- GEMM1: G/U = Xg @ W (gate or up by blockIdx.x>>3) ----------------
__global__ __launch_bounds__(256, 1) void gemm1_mma() {
    extern __shared__ char smem[];
    const int m0 = blockIdx.y * BM;
    if (m0 >= g_off[NSEG]) return;
    const int ntile = blockIdx.x & 7, gu = blockIdx.x >> 3;
    const int n0 = ntile * BN;
    int seg = 0;
#pragma unroll
    for (int s = 1; s < NSEG; s++) if (m0 >= g_off[s]) seg = s;

    const int tid = threadIdx.x, lane = tid & 31, wid = tid >> 5;
    const int wm = wid & 3, wn = wid >> 2;

    const __nv_bfloat16* gAh = g_xhi + (size_t)m0 * DM;
    const __nv_bfloat16* gAl = g_xlo + (size_t)m0 * DM;
    const __nv_bfloat16* gBh = (gu ? g_wuhi : g_wghi) + ((size_t)seg * HS + n0) * DM;
    const __nv_bfloat16* gBl = (gu ? g_wulo : g_wglo) + ((size_t)seg * HS + n0) * DM;

    float acc[2][8][4];
    gemm_mainloop(s2u(smem), gAh, gAl, gBh, gBl, tid, acc);

    float* __restrict__ C = gu ? g_U : g_G;
#pragma unroll
    for (int mt = 0; mt < 2; mt++) {
        const int r = m0 + wm * 32 + mt * 16 + (lane >> 2);
#pragma unroll
        for (int nt = 0; nt < 8; nt++) {
            const int cc = n0 + wn * 64 + nt * 8 + (lane & 3) * 2;
            *reinterpret_cast<float2*>(C + (size_t)r * HS + cc) =
                make_float2(acc[mt][nt][0], acc[mt][nt][1]);
            *reinterpret_cast<float2*>(C + (size_t)(r + 8) * HS + cc) =
                make_float2(acc[mt][nt][2], acc[mt][nt][3]);
        }
    }
}

// ---------------- SwiGLU: h = silu(G)*U -> bf16 hi/lo ----------------
__global__ void k_swiglu() {
    size_t i4 = ((size_t)blockIdx.x * blockDim.x + threadIdx.x) * 4;
    if (i4 >= (size_t)MAX_ROWS * HS) return;
    float4 g4 = *reinterpret_cast<float4*>(&g_G[i4]);
    float4 u4 = *reinterpret_cast<float4*>(&g_U[i4]);
    float h0 = (g4.x / (1.f + __expf(-g4.x))) * u4.x;
    float h1 = (g4.y / (1.f + __expf(-g4.y))) * u4.y;
    float h2 = (g4.z / (1.f + __expf(-g4.z))) * u4.z;
    float h3 = (g4.w / (1.f + __expf(-g4.w))) * u4.w;
    __nv_bfloat16 a, b, c, d, e, f, g, h;
    split2(h0, a, b); split2(h1, c, d); split2(h2, e, f); split2(h3, g, h);
    *reinterpret_cast<uint2*>(g_hhi + i4) = make_uint2(pack2(a, c), pack2(e, g));
    *reinterpret_cast<uint2*>(g_hlo + i4) = make_uint2(pack2(b, d), pack2(f, h));
}

// ---------------- GEMM2: out[token] = H @ down_w[seg] ----------------
__global__ __launch_bounds__(256, 1) void gemm2_mma(float* __restrict__ out) {
    extern __shared__ char smem[];
    const int m0 = blockIdx.y * BM;
    if (m0 >= g_off[NSEG]) return;
    const int n0 = blockIdx.x * BN;
    int seg = 0;
#pragma unroll
    for (int s = 1; s < NSEG; s++) if (m0 >= g_off[s]) seg = s;

    const int tid = threadIdx.x, lane = tid & 31, wid = tid >> 5;
    const int wm = wid & 3, wn = wid >> 2;

    const __nv_bfloat16* gAh = g_hhi + (size_t)m0 * HS;
    const __nv_bfloat16* gAl = g_hlo + (size_t)m0 * HS;
    const __nv_bfloat16* gBh = g_wdhi + ((size_t)seg * DM + n0) * HS;
    const __nv_bfloat16* gBl = g_wdlo + ((size_t)seg * DM + n0) * HS;

    float acc[2][8][4];
    gemm_mainloop(s2u(smem), gAh, gAl, gBh, gBl, tid, acc);

#pragma unroll
    for (int mt = 0; mt < 2; mt++) {
        const int rbase = m0 + wm * 32 + mt * 16 + (lane >> 2);
        const int t0 = g_perm[rbase];
        const int t1 = g_perm[rbase + 8];
#pragma unroll
        for (int nt = 0; nt < 8; nt++) {
            const int cc = n0 + wn * 64 + nt * 8 + (lane & 3) * 2;
            if (t0 >= 0)
                *reinterpret_cast<float2*>(out + (size_t)t0 * DM + cc) =
                    make_float2(acc[mt][nt][0], acc[mt][nt][1]);
            if (t1 >= 0)
                *reinterpret_cast<float2*>(out + (size_t)t1 * DM + cc) =
                    make_float2(acc[mt][nt][2], acc[mt][nt][3]);
        }
    }
}

// ---------------- entry point ----------------
extern "C" void kernel_launch(void* const* d_in, const int* in_sizes, int n_in,
                              void* d_out, int out_size)
{
    const float* x   = (const float*)d_in[0];
    const float* gw  = (const float*)d_in[1];
    const float* uw  = (const float*)d_in[2];
    const float* dw  = (const float*)d_in[3];
    const int*   idx = (const int*)d_in[4];
    float* out = (float*)d_out;

    static int smem_set = 0;
    if (!smem_set) {
        cudaFuncSetAttribute(gemm1_mma, cudaFuncAttributeMaxDynamicSharedMemorySize, SMEM_G);
        cudaFuncSetAttribute(gemm2_mma, cudaFuncAttributeMaxDynamicSharedMemorySize, SMEM_G);
        smem_set = 1;
    }

    k_prep<<<(MAX_ROWS + 255) / 256, 256>>>();
    k_detect<<<(NT / 2 + 255) / 256, 256>>>(idx);
    k_count<<<(NT + 255) / 256, 256>>>(idx);
    k_off<<<1, 32>>>();
    k_scatter<<<(NT + 255) / 256, 256>>>(idx);

    k_convw<<<dim3(32, 32, 12), dim3(32, 8)>>>(gw, uw, dw);
    k_convx<<<(MAX_ROWS * (DM / 4) + 255) / 256, 256>>>(x);

    gemm1_mma<<<dim3(16, MTILES), 256, SMEM_G>>>();

    size_t nelem = (size_t)MAX_ROWS * HS;
    k_swiglu<<<(unsigned)((nelem / 4 + 255) / 256), 256>>>();

    gemm2_mma<<<dim3(8, MTILES), 256, SMEM_G>>>(out);
}

// round 7
// speedup vs baseline: 2.3774x; 1.0601x over previous
#include <cuda_runtime.h>
#include <cuda_bf16.h>
#include <math.h>
#include <stdint.h>

// ---------------- problem constants ----------------
#define NT   16384
#define DM   1024
#define HS   1024
#define NSEG 4
#define KDIM 1024               // K of both GEMMs

#define BM   128
#define BN   256
#define BK   32
#define NKIT (KDIM / BK)        // 32

#define MAX_ROWS (NT + NSEG * BM)   // 16896
#define MTILES   (MAX_ROWS / BM)    // 132

// SMEM stage: A hi/lo (128 rows) + B hi/lo (256 rows), row = 32 bf16 = 64B -> 80B padded
#define ROWB     80
#define TILE128  (128 * ROWB)       // 10240
#define BTILE    (256 * ROWB)       // 20480
#define STAGEB   (2 * TILE128 + 2 * BTILE)  // 61440
#define NSTAGE   3
#define SMEM_G   (NSTAGE * STAGEB)  // 184320
#define EPI_STRIDE 268              // fp32 epilogue smem stride (conflict-spread, 16B aligned)

// ---------------- device scratch ----------------
__device__ int g_perm[MAX_ROWS];
__device__ int g_count[NSEG];
__device__ int g_cursor[NSEG];
__device__ int g_off[NSEG + 1];
__device__ int g_is32;

__device__ __nv_bfloat16 g_xhi[(size_t)MAX_ROWS * DM];
__device__ __nv_bfloat16 g_xlo[(size_t)MAX_ROWS * DM];
__device__ __nv_bfloat16 g_hhi[(size_t)MAX_ROWS * HS];
__device__ __nv_bfloat16 g_hlo[(size_t)MAX_ROWS * HS];
// weights K-major [seg][n][k], split hi/lo
__device__ __nv_bfloat16 g_wghi[(size_t)NSEG * HS * DM];
__device__ __nv_bfloat16 g_wglo[(size_t)NSEG * HS * DM];
__device__ __nv_bfloat16 g_wuhi[(size_t)NSEG * HS * DM];
__device__ __nv_bfloat16 g_wulo[(size_t)NSEG * HS * DM];
__device__ __nv_bfloat16 g_wdhi[(size_t)NSEG * DM * HS];
__device__ __nv_bfloat16 g_wdlo[(size_t)NSEG * DM * HS];

// ---------------- small helpers ----------------
__device__ __forceinline__ uint32_t s2u(const void* p) {
    return (uint32_t)__cvta_generic_to_shared(p);
}
__device__ __forceinline__ void cpa16(uint32_t dst, const void* src) {
    asm volatile("cp.async.cg.shared.global [%0], [%1], 16;" :: "r"(dst), "l"(src));
}
#define CP_COMMIT() asm volatile("cp.async.commit_group;" ::: "memory")
#define CP_WAIT1()  asm volatile("cp.async.wait_group 1;" ::: "memory")
#define CP_WAIT0()  asm volatile("cp.async.wait_group 0;" ::: "memory")

__device__ __forceinline__ void ldmx4(uint32_t* r, uint32_t addr) {
    asm volatile("ldmatrix.sync.aligned.m8n8.x4.shared.b16 {%0,%1,%2,%3}, [%4];"
        : "=r"(r[0]), "=r"(r[1]), "=r"(r[2]), "=r"(r[3]) : "r"(addr));
}
__device__ __forceinline__ void mma16816(float* c, const uint32_t* a, const uint32_t* b) {
    asm volatile(
        "mma.sync.aligned.m16n8k16.row.col.f32.bf16.bf16.f32 "
        "{%0,%1,%2,%3}, {%4,%5,%6,%7}, {%8,%9}, {%0,%1,%2,%3};"
        : "+f"(c[0]), "+f"(c[1]), "+f"(c[2]), "+f"(c[3])
        : "r"(a[0]), "r"(a[1]), "r"(a[2]), "r"(a[3]), "r"(b[0]), "r"(b[1]));
}

__device__ __forceinline__ void split2(float v, __nv_bfloat16& h, __nv_bfloat16& l) {
    h = __float2bfloat16(v);
    l = __float2bfloat16(v - __bfloat162float(h));
}
__device__ __forceinline__ uint32_t pack2(__nv_bfloat16 a, __nv_bfloat16 b) {
    return ((uint32_t)__bfloat16_as_ushort(b) << 16) | __bfloat16_as_ushort(a);
}

// ---------------- routing kernels ----------------
__global__ void k_prep() {
    int i = blockIdx.x * blockDim.x + threadIdx.x;
    if (i < MAX_ROWS) g_perm[i] = -1;
    if (i < NSEG) { g_count[i] = 0; g_cursor[i] = 0; }
    if (i == 0) g_is32 = 0;
}
__global__ void k_detect(const int* __restrict__ idx32) {
    int i = blockIdx.x * blockDim.x + threadIdx.x;
    if (i < NT / 2 && idx32[2 * i + 1] != 0) atomicExch(&g_is32, 1);
}
__device__ __forceinline__ int seg_of(const int* __restrict__ idx32, int i) {
    return (g_is32 ? idx32[i] : idx32[2 * i]) & (NSEG - 1);
}
__global__ void k_count(const int* __restrict__ idx32) {
    int i = blockIdx.x * blockDim.x + threadIdx.x;
    if (i < NT) atomicAdd(&g_count[seg_of(idx32, i)], 1);
}
__global__ void k_off() {
    if (threadIdx.x == 0 && blockIdx.x == 0) {
        int o = 0;
        for (int s = 0; s < NSEG; s++) {
            g_off[s] = o;
            o += ((g_count[s] + BM - 1) / BM) * BM;
        }
        g_off[NSEG] = o;
    }
}
__global__ void k_scatter(const int* __restrict__ idx32) {
    int i = blockIdx.x * blockDim.x + threadIdx.x;
    if (i < NT) {
        int s = seg_of(idx32, i);
        g_perm[g_off[s] + atomicAdd(&g_cursor[s], 1)] = i;
    }
}

// ---------------- conversion: gathered x -> bf16 hi/lo ----------------
__global__ void k_convx(const float* __restrict__ x) {
    int gid = blockIdx.x * blockDim.x + threadIdx.x;
    if (gid >= MAX_ROWS * (DM / 4)) return;
    int r = gid >> 8;
    int c = (gid & 255) << 2;
    int t = g_perm[r];
    float4 v = (t >= 0) ? *reinterpret_cast<const float4*>(x + (size_t)t * DM + c)
                        : make_float4(0.f, 0.f, 0.f, 0.f);
    __nv_bfloat16 hx, lx, hy, ly, hz, lz, hw, lw;
    split2(v.x, hx, lx); split2(v.y, hy, ly);
    split2(v.z, hz, lz); split2(v.w, hw, lw);
    size_t o = (size_t)r * DM + c;
    *reinterpret_cast<uint2*>(g_xhi + o) = make_uint2(pack2(hx, hy), pack2(hz, hw));
    *reinterpret_cast<uint2*>(g_xlo + o) = make_uint2(pack2(lx, ly), pack2(lz, lw));
}

// ---------------- conversion: weights fp32 [k][n] -> bf16 hi/lo [n][k] ----------------
__global__ void k_convw(const float* __restrict__ gw, const float* __restrict__ uw,
                        const float* __restrict__ dw) {
    __shared__ float tile[32][33];
    int mat = blockIdx.z >> 2, seg = blockIdx.z & 3;
    const float* W = (mat == 0 ? gw : (mat == 1 ? uw : dw)) + (size_t)seg * DM * HS;
    __nv_bfloat16* Ohi = (mat == 0 ? g_wghi : (mat == 1 ? g_wuhi : g_wdhi)) + (size_t)seg * DM * HS;
    __nv_bfloat16* Olo = (mat == 0 ? g_wglo : (mat == 1 ? g_wulo : g_wdlo)) + (size_t)seg * DM * HS;
    int n0 = blockIdx.x * 32, k0 = blockIdx.y * 32;
    int tx = threadIdx.x, ty = threadIdx.y;
#pragma unroll
    for (int i = 0; i < 4; i++)
        tile[ty + 8 * i][tx] = W[(size_t)(k0 + ty + 8 * i) * 1024 + n0 + tx];
    __syncthreads();
#pragma unroll
    for (int i = 0; i < 4; i++) {
        float v = tile[tx][ty + 8 * i];
        __nv_bfloat16 h, l; split2(v, h, l);
        size_t o = (size_t)(n0 + ty + 8 * i) * 1024 + k0 + tx;
        Ohi[o] = h; Olo[o] = l;
    }
}

// ---------------- stage loader ----------------
// A: 128 rows (hi+lo tiles); B: 256 rows (hi+lo), rows 0-127 from B0, 128-255 from B1.
__device__ __forceinline__ void ld_stage(uint32_t sb,
        const __nv_bfloat16* gAh, const __nv_bfloat16* gAl,
        const __nv_bfloat16* B0h, const __nv_bfloat16* B0l,
        const __nv_bfloat16* B1h, const __nv_bfloat16* B1l,
        int kc, int tid) {
    const int ko = kc * BK;
#pragma unroll
    for (int q = 0; q < 2; q++) {
        int id = q * 256 + tid;
        int row = id >> 2, c = id & 3;
        uint32_t d = sb + row * ROWB + c * 16;
        const size_t so = (size_t)row * KDIM + ko + c * 8;
        cpa16(d, gAh + so);
        cpa16(d + TILE128, gAl + so);
    }
#pragma unroll
    for (int q = 0; q < 4; q++) {
        int id = q * 256 + tid;
        int row = id >> 2, c = id & 3;
        const __nv_bfloat16* sh = (row < 128) ? B0h : (B1h - (size_t)128 * KDIM);
        const __nv_bfloat16* sl = (row < 128) ? B0l : (B1l - (size_t)128 * KDIM);
        uint32_t d = sb + 2 * TILE128 + row * ROWB + c * 16;
        const size_t so = (size_t)row * KDIM + ko + c * 8;
        cpa16(d, sh + so);
        cpa16(d + BTILE, sl + so);
    }
}

// ---------------- GEMM mainloop: CTA 128x256, 8 warps of 64x64 ----------------
__device__ __forceinline__ void gemm_mainloop(uint32_t sbase,
        const __nv_bfloat16* gAh, const __nv_bfloat16* gAl,
        const __nv_bfloat16* B0h, const __nv_bfloat16* B0l,
        const __nv_bfloat16* B1h, const __nv_bfloat16* B1l,
        int tid, float acc[4][8][4]) {
    const int lane = tid & 31, wid = tid >> 5;
    const int wm = wid & 1, wn = wid >> 1;

#pragma unroll
    for (int i = 0; i < 4; i++)
#pragma unroll
        for (int j = 0; j < 8; j++)
#pragma unroll
            for (int q = 0; q < 4; q++) acc[i][j][q] = 0.f;

    ld_stage(sbase,          gAh, gAl, B0h, B0l, B1h, B1l, 0, tid); CP_COMMIT();
    ld_stage(sbase + STAGEB, gAh, gAl, B0h, B0l, B1h, B1l, 1, tid); CP_COMMIT();

    const int a_r  = lane & 15;
    const int a_kb = (lane >> 4) << 4;
    const int b_r  = ((lane >> 4) << 3) + (lane & 7);
    const int b_kb = ((lane >> 3) & 1) << 4;
    const int a_row0 = wm * 64;
    const int b_col0 = wn * 64;

    for (int it = 0; it < NKIT; it++) {
        if (it + 2 < NKIT) CP_WAIT1(); else CP_WAIT0();
        __syncthreads();
        if (it + 2 < NKIT) {
            ld_stage(sbase + ((it + 2) % NSTAGE) * STAGEB,
                     gAh, gAl, B0h, B0l, B1h, B1l, it + 2, tid);
            CP_COMMIT();
        }
        const uint32_t sb = sbase + (it % NSTAGE) * STAGEB;
        const uint32_t sB = sb + 2 * TILE128;
#pragma unroll
        for (int ks = 0; ks < 2; ks++) {
            const int kb = ks * 32;
            uint32_t aH[4][4], aL[4][4];
#pragma unroll
            for (int mt = 0; mt < 4; mt++) {
                uint32_t ad = sb + (a_row0 + mt * 16 + a_r) * ROWB + kb + a_kb;
                ldmx4(aH[mt], ad);
                ldmx4(aL[mt], ad + TILE128);
            }
#pragma unroll
            for (int nh = 0; nh < 2; nh++) {
                uint32_t bH[4][2], bL[4][2];
#pragma unroll
                for (int p = 0; p < 2; p++) {
                    uint32_t bd = sB + (b_col0 + nh * 32 + p * 16 + b_r) * ROWB + kb + b_kb;
                    uint32_t r[4];
                    ldmx4(r, bd);
                    bH[2 * p][0] = r[0]; bH[2 * p][1] = r[1];
                    bH[2 * p + 1][0] = r[2]; bH[2 * p + 1][1] = r[3];
                    ldmx4(r, bd + BTILE);
                    bL[2 * p][0] = r[0]; bL[2 * p][1] = r[1];
                    bL[2 * p + 1][0] = r[2]; bL[2 * p + 1][1] = r[3];
                }
#pragma unroll
                for (int mt = 0; mt < 4; mt++)
#pragma unroll
                    for (int q = 0; q < 4; q++) {
                        float* c = acc[mt][nh * 4 + q];
                        mma16816(c, aH[mt], bH[q]);
                        mma16816(c, aH[mt], bL[q]);
                        mma16816(c, aL[mt], bH[q]);
                    }
            }
        }
    }
}

// ---------------- GEMM1: [gate|up] fused, SwiGLU epilogue -> bf16 hidden ----------------
__global__ __launch_bounds__(256, 1) void gemm1_mma() {
    extern __shared__ char smem[];
    const int m0 = blockIdx.y * BM;
    if (m0 >= g_off[NSEG]) return;
    const int h0 = blockIdx.x * 128;
    int seg = 0;
#pragma unroll
    for (int s = 1; s < NSEG; s++) if (m0 >= g_off[s]) seg = s;

    const int tid = threadIdx.x, lane = tid & 31, wid = tid >> 5;
    const int wm = wid & 1, wn = wid >> 1;

    const __nv_bfloat16* gAh = g_xhi + (size_t)m0 * DM;
    const __nv_bfloat16* gAl = g_xlo + (size_t)m0 * DM;
    const size_t wo = ((size_t)seg * HS + h0) * DM;

    float acc[4][8][4];
    gemm_mainloop(s2u(smem), gAh, gAl,
                  g_wghi + wo, g_wglo + wo, g_wuhi + wo, g_wulo + wo,
                  tid, acc);

    // stage fp32 acc to smem (cols 0-127 = gate, 128-255 = up)
    __syncthreads();
    float* S = reinterpret_cast<float*>(smem);
#pragma unroll
    for (int mt = 0; mt < 4; mt++) {
        const int r = wm * 64 + mt * 16 + (lane >> 2);
#pragma unroll
        for (int nt = 0; nt < 8; nt++) {
            const int c = wn * 64 + nt * 8 + (lane & 3) * 2;
            *reinterpret_cast<float2*>(S + (size_t)r * EPI_STRIDE + c) =
                make_float2(acc[mt][nt][0], acc[mt][nt][1]);
            *reinterpret_cast<float2*>(S + (size_t)(r + 8) * EPI_STRIDE + c) =
                make_float2(acc[mt][nt][2], acc[mt][nt][3]);
        }
    }
    __syncthreads();

    // swiglu + split to bf16 hi/lo
    const int row = tid >> 1, half = tid & 1;
    const float* Sg = S + (size_t)row * EPI_STRIDE + half * 64;
    const float* Su = Sg + 128;
    __nv_bfloat16* dh = g_hhi + (size_t)(m0 + row) * HS + h0 + half * 64;
    __nv_bfloat16* dl = g_hlo + (size_t)(m0 + row) * HS + h0 + half * 64;
#pragma unroll
    for (int j = 0; j < 16; j++) {
        float4 gv = *reinterpret_cast<const float4*>(Sg + 4 * j);
        float4 uv = *reinterpret_cast<const float4*>(Su + 4 * j);
        float h0v = (gv.x / (1.f + __expf(-gv.x))) * uv.x;
        float h1v = (gv.y / (1.f + __expf(-gv.y))) * uv.y;
        float h2v = (gv.z / (1.f + __expf(-gv.z))) * uv.z;
        float h3v = (gv.w / (1.f + __expf(-gv.w))) * uv.w;
        __nv_bfloat16 a, b, c, d, e, f, g, h;
        split2(h0v, a, b); split2(h1v, c, d); split2(h2v, e, f); split2(h3v, g, h);
        *reinterpret_cast<uint2*>(dh + 4 * j) = make_uint2(pack2(a, c), pack2(e, g));
        *reinterpret_cast<uint2*>(dl + 4 * j) = make_uint2(pack2(b, d), pack2(f, h));
    }
}

// ---------------- GEMM2: out[token] = H @ down_w[seg], scatter ----------------
__global__ __launch_bounds__(256, 1) void gemm2_mma(float* __restrict__ out) {
    extern __shared__ char smem[];
    const int m0 = blockIdx.y * BM;
    if (m0 >= g_off[NSEG]) return;
    const int n0 = blockIdx.x * BN;
    int seg = 0;
#pragma unroll
    for (int s = 1; s < NSEG; s++) if (m0 >= g_off[s]) seg = s;

    const int tid = threadIdx.x, lane = tid & 31, wid = tid >> 5;
    const int wm = wid & 1, wn = wid >> 1;

    const __nv_bfloat16* gAh = g_hhi + (size_t)m0 * HS;
    const __nv_bfloat16* gAl = g_hlo + (size_t)m0 * HS;
    const size_t wo = ((size_t)seg * DM + n0) * HS;
    const __nv_bfloat16* Bh = g_wdhi + wo;
    const __nv_bfloat16* Bl = g_wdlo + wo;

    float acc[4][8][4];
    gemm_mainloop(s2u(smem), gAh, gAl,
                  Bh, Bl, Bh + (size_t)128 * HS, Bl + (size_t)128 * HS,
                  tid, acc);

#pragma unroll
    for (int mt = 0; mt < 4; mt++) {
        const int rb = m0 + wm * 64 + mt * 16 + (lane >> 2);
        const int t0 = g_perm[rb];
        const int t1 = g_perm[rb + 8];
#pragma unroll
        for (int nt = 0; nt < 8; nt++) {
            const int c = n0 + wn * 64 + nt * 8 + (lane & 3) * 2;
            if (t0 >= 0)
                *reinterpret_cast<float2*>(out + (size_t)t0 * DM + c) =
                    make_float2(acc[mt][nt][0], acc[mt][nt][1]);
            if (t1 >= 0)
                *reinterpret_cast<float2*>(out + (size_t)t1 * DM + c) =
                    make_float2(acc[mt][nt][2], acc[mt][nt][3]);
        }
    }
}

// ---------------- entry point ----------------
extern "C" void kernel_launch(void* const* d_in, const int* in_sizes, int n_in,
                              void* d_out, int out_size)
{
    const float* x   = (const float*)d_in[0];
    const float* gw  = (const float*)d_in[1];
    const float* uw  = (const float*)d_in[2];
    const float* dw  = (const float*)d_in[3];
    const int*   idx = (const int*)d_in[4];
    float* out = (float*)d_out;

    static int smem_set = 0;
    if (!smem_set) {
        cudaFuncSetAttribute(gemm1_mma, cudaFuncAttributeMaxDynamicSharedMemorySize, SMEM_G);
        cudaFuncSetAttribute(gemm2_mma, cudaFuncAttributeMaxDynamicSharedMemorySize, SMEM_G);
        smem_set = 1;
    }

    k_prep<<<(MAX_ROWS + 255) / 256, 256>>>();
    k_detect<<<(NT / 2 + 255) / 256, 256>>>(idx);
    k_count<<<(NT + 255) / 256, 256>>>(idx);
    k_off<<<1, 32>>>();
    k_scatter<<<(NT + 255) / 256, 256>>>(idx);

    k_convw<<<dim3(32, 32, 12), dim3(32, 8)>>>(gw, uw, dw);
    k_convx<<<(MAX_ROWS * (DM / 4) + 255) / 256, 256>>>(x);

    gemm1_mma<<<dim3(HS / 128, MTILES), 256, SMEM_G>>>();
    gemm2_mma<<<dim3(DM / BN, MTILES), 256, SMEM_G>>>(out);
}

// round 8
// speedup vs baseline: 2.3777x; 1.0001x over previous
#include <cuda_runtime.h>
#include <cuda_bf16.h>
#include <math.h>
#include <stdint.h>

// ---------------- problem constants ----------------
#define NT   16384
#define DM   1024
#define HS   1024
#define NSEG 4
#define KDIM 1024               // K of both GEMMs

#define BM   128
#define BN   256
#define BK   32
#define NKIT (KDIM / BK)        // 32

#define MAX_ROWS (NT + NSEG * BM)   // 16896
#define MTILES   (MAX_ROWS / BM)    // 132

// SMEM stage: A hi/lo (128 rows) + B hi/lo (256 rows), row = 32 bf16 = 64B -> 80B padded
#define ROWB     80
#define TILE128  (128 * ROWB)       // 10240
#define BTILE    (256 * ROWB)       // 20480
#define STAGEB   (2 * TILE128 + 2 * BTILE)  // 61440
#define NSTAGE   3
#define SMEM_G   (NSTAGE * STAGEB)  // 184320
#define EPI_STRIDE 268              // fp32 epilogue smem stride (conflict-spread, 16B aligned)

// ---------------- device scratch ----------------
__device__ int g_perm[MAX_ROWS];
__device__ int g_count[NSEG];
__device__ int g_cursor[NSEG];
__device__ int g_off[NSEG + 1];
__device__ int g_is32;

__device__ __nv_bfloat16 g_xhi[(size_t)MAX_ROWS * DM];
__device__ __nv_bfloat16 g_xlo[(size_t)MAX_ROWS * DM];
__device__ __nv_bfloat16 g_hhi[(size_t)MAX_ROWS * HS];
__device__ __nv_bfloat16 g_hlo[(size_t)MAX_ROWS * HS];
// weights K-major [seg][n][k], split hi/lo
__device__ __nv_bfloat16 g_wghi[(size_t)NSEG * HS * DM];
__device__ __nv_bfloat16 g_wglo[(size_t)NSEG * HS * DM];
__device__ __nv_bfloat16 g_wuhi[(size_t)NSEG * HS * DM];
__device__ __nv_bfloat16 g_wulo[(size_t)NSEG * HS * DM];
__device__ __nv_bfloat16 g_wdhi[(size_t)NSEG * DM * HS];
__device__ __nv_bfloat16 g_wdlo[(size_t)NSEG * DM * HS];

// ---------------- small helpers ----------------
__device__ __forceinline__ uint32_t s2u(const void* p) {
    return (uint32_t)__cvta_generic_to_shared(p);
}
__device__ __forceinline__ void cpa16(uint32_t dst, const void* src) {
    asm volatile("cp.async.cg.shared.global [%0], [%1], 16;" :: "r"(dst), "l"(src));
}
#define CP_COMMIT() asm volatile("cp.async.commit_group;" ::: "memory")
#define CP_WAIT1()  asm volatile("cp.async.wait_group 1;" ::: "memory")
#define CP_WAIT0()  asm volatile("cp.async.wait_group 0;" ::: "memory")

__device__ __forceinline__ void ldmx4(uint32_t* r, uint32_t addr) {
    asm volatile("ldmatrix.sync.aligned.m8n8.x4.shared.b16 {%0,%1,%2,%3}, [%4];"
        : "=r"(r[0]), "=r"(r[1]), "=r"(r[2]), "=r"(r[3]) : "r"(addr));
}
__device__ __forceinline__ void mma16816(float* c, const uint32_t* a, const uint32_t* b) {
    asm volatile(
        "mma.sync.aligned.m16n8k16.row.col.f32.bf16.bf16.f32 "
        "{%0,%1,%2,%3}, {%4,%5,%6,%7}, {%8,%9}, {%0,%1,%2,%3};"
        : "+f"(c[0]), "+f"(c[1]), "+f"(c[2]), "+f"(c[3])
        : "r"(a[0]), "r"(a[1]), "r"(a[2]), "r"(a[3]), "r"(b[0]), "r"(b[1]));
}

__device__ __forceinline__ void split2(float v, __nv_bfloat16& h, __nv_bfloat16& l) {
    h = __float2bfloat16(v);
    l = __float2bfloat16(v - __bfloat162float(h));
}
__device__ __forceinline__ uint32_t pack2(__nv_bfloat16 a, __nv_bfloat16 b) {
    return ((uint32_t)__bfloat16_as_ushort(b) << 16) | __bfloat16_as_ushort(a);
}

// ---------------- routing kernels ----------------
__global__ void k_prep() {
    int i = blockIdx.x * blockDim.x + threadIdx.x;
    if (i < MAX_ROWS) g_perm[i] = -1;
    if (i < NSEG) { g_count[i] = 0; g_cursor[i] = 0; }
    if (i == 0) g_is32 = 0;
}
__global__ void k_detect(const int* __restrict__ idx32) {
    int i = blockIdx.x * blockDim.x + threadIdx.x;
    if (i < NT / 2 && idx32[2 * i + 1] != 0) atomicExch(&g_is32, 1);
}
__device__ __forceinline__ int seg_of(const int* __restrict__ idx32, int i) {
    return (g_is32 ? idx32[i] : idx32[2 * i]) & (NSEG - 1);
}
__global__ void k_count(const int* __restrict__ idx32) {
    int i = blockIdx.x * blockDim.x + threadIdx.x;
    if (i < NT) atomicAdd(&g_count[seg_of(idx32, i)], 1);
}
__global__ void k_off() {
    if (threadIdx.x == 0 && blockIdx.x == 0) {
        int o = 0;
        for (int s = 0; s < NSEG; s++) {
            g_off[s] = o;
            o += ((g_count[s] + BM - 1) / BM) * BM;
        }
        g_off[NSEG] = o;
    }
}
__global__ void k_scatter(const int* __restrict__ idx32) {
    int i = blockIdx.x * blockDim.x + threadIdx.x;
    if (i < NT) {
        int s = seg_of(idx32, i);
        g_perm[g_off[s] + atomicAdd(&g_cursor[s], 1)] = i;
    }
}

// ---------------- conversion: gathered x -> bf16 hi/lo ----------------
__global__ void k_convx(const float* __restrict__ x) {
    int gid = blockIdx.x * blockDim.x + threadIdx.x;
    if (gid >= MAX_ROWS * (DM / 4)) return;
    int r = gid >> 8;
    int c = (gid & 255) << 2;
    int t = g_perm[r];
    float4 v = (t >= 0) ? *reinterpret_cast<const float4*>(x + (size_t)t * DM + c)
                        : make_float4(0.f, 0.f, 0.f, 0.f);
    __nv_bfloat16 hx, lx, hy, ly, hz, lz, hw, lw;
    split2(v.x, hx, lx); split2(v.y, hy, ly);
    split2(v.z, hz, lz); split2(v.w, hw, lw);
    size_t o = (size_t)r * DM + c;
    *reinterpret_cast<uint2*>(g_xhi + o) = make_uint2(pack2(hx, hy), pack2(hz, hw));
    *reinterpret_cast<uint2*>(g_xlo + o) = make_uint2(pack2(lx, ly), pack2(lz, lw));
}

// ---------------- conversion: weights fp32 [k][n] -> bf16 hi/lo [n][k] ----------------
__global__ void k_convw(const float* __restrict__ gw, const float* __restrict__ uw,
                        const float* __restrict__ dw) {
    __shared__ float tile[32][33];
    int mat = blockIdx.z >> 2, seg = blockIdx.z & 3;
    const float* W = (mat == 0 ? gw : (mat == 1 ? uw : dw)) + (size_t)seg * DM * HS;
    __nv_bfloat16* Ohi = (mat == 0 ? g_wghi : (mat == 1 ? g_wuhi : g_wdhi)) + (size_t)seg * DM * HS;
    __nv_bfloat16* Olo = (mat == 0 ? g_wglo : (mat == 1 ? g_wulo : g_wdlo)) + (size_t)seg * DM * HS;
    int n0 = blockIdx.x * 32, k0 = blockIdx.y * 32;
    int tx = threadIdx.x, ty = threadIdx.y;
#pragma unroll
    for (int i = 0; i < 4; i++)
        tile[ty + 8 * i][tx] = W[(size_t)(k0 + ty + 8 * i) * 1024 + n0 + tx];
    __syncthreads();
#pragma unroll
    for (int i = 0; i < 4; i++) {
        float v = tile[tx][ty + 8 * i];
        __nv_bfloat16 h, l; split2(v, h, l);
        size_t o = (size_t)(n0 + ty + 8 * i) * 1024 + k0 + tx;
        Ohi[o] = h; Olo[o] = l;
    }
}

// ---------------- stage loader ----------------
// A: 128 rows (hi+lo tiles); B: 256 rows (hi+lo), rows 0-127 from B0, 128-255 from B1.
__device__ __forceinline__ void ld_stage(uint32_t sb,
        const __nv_bfloat16* gAh, const __nv_bfloat16* gAl,
        const __nv_bfloat16* B0h, const __nv_bfloat16* B0l,
        const __nv_bfloat16* B1h, const __nv_bfloat16* B1l,
        int kc, int tid) {
    const int ko = kc * BK;
#pragma unroll
    for (int q = 0; q < 2; q++) {
        int id = q * 256 + tid;
        int row = id >> 2, c = id & 3;
        uint32_t d = sb + row * ROWB + c * 16;
        const size_t so = (size_t)row * KDIM + ko + c * 8;
        cpa16(d, gAh + so);
        cpa16(d + TILE128, gAl + so);
    }
#pragma unroll
    for (int q = 0; q < 4; q++) {
        int id = q * 256 + tid;
        int row = id >> 2, c = id & 3;
        const __nv_bfloat16* sh = (row < 128) ? B0h : (B1h - (size_t)128 * KDIM);
        const __nv_bfloat16* sl = (row < 128) ? B0l : (B1l - (size_t)128 * KDIM);
        uint32_t d = sb + 2 * TILE128 + row * ROWB + c * 16;
        const size_t so = (size_t)row * KDIM + ko + c * 8;
        cpa16(d, sh + so);
        cpa16(d + BTILE, sl + so);
    }
}

// ---------------- GEMM mainloop: CTA 128x256, 8 warps of 64x64 ----------------
// Product-major MMA issue: 16 independent MMAs per emulation product to break
// accumulator RAW chains (hh-batch, then hl-batch, then lh-batch).
__device__ __forceinline__ void gemm_mainloop(uint32_t sbase,
        const __nv_bfloat16* gAh, const __nv_bfloat16* gAl,
        const __nv_bfloat16* B0h, const __nv_bfloat16* B0l,
        const __nv_bfloat16* B1h, const __nv_bfloat16* B1l,
        int tid, float acc[4][8][4]) {
    const int lane = tid & 31, wid = tid >> 5;
    const int wm = wid & 1, wn = wid >> 1;

#pragma unroll
    for (int i = 0; i < 4; i++)
#pragma unroll
        for (int j = 0; j < 8; j++)
#pragma unroll
            for (int q = 0; q < 4; q++) acc[i][j][q] = 0.f;

    ld_stage(sbase,          gAh, gAl, B0h, B0l, B1h, B1l, 0, tid); CP_COMMIT();
    ld_stage(sbase + STAGEB, gAh, gAl, B0h, B0l, B1h, B1l, 1, tid); CP_COMMIT();

    const int a_r  = lane & 15;
    const int a_kb = (lane >> 4) << 4;
    const int b_r  = ((lane >> 4) << 3) + (lane & 7);
    const int b_kb = ((lane >> 3) & 1) << 4;
    const int a_row0 = wm * 64;
    const int b_col0 = wn * 64;

    for (int it = 0; it < NKIT; it++) {
        if (it + 2 < NKIT) CP_WAIT1(); else CP_WAIT0();
        __syncthreads();
        if (it + 2 < NKIT) {
            ld_stage(sbase + ((it + 2) % NSTAGE) * STAGEB,
                     gAh, gAl, B0h, B0l, B1h, B1l, it + 2, tid);
            CP_COMMIT();
        }
        const uint32_t sb = sbase + (it % NSTAGE) * STAGEB;
        const uint32_t sB = sb + 2 * TILE128;
#pragma unroll
        for (int ks = 0; ks < 2; ks++) {
            const int kb = ks * 32;
            uint32_t aH[4][4], aL[4][4];
#pragma unroll
            for (int mt = 0; mt < 4; mt++) {
                uint32_t ad = sb + (a_row0 + mt * 16 + a_r) * ROWB + kb + a_kb;
                ldmx4(aH[mt], ad);
                ldmx4(aL[mt], ad + TILE128);
            }
#pragma unroll
            for (int nh = 0; nh < 2; nh++) {
                uint32_t bH[4][2], bL[4][2];
#pragma unroll
                for (int p = 0; p < 2; p++) {
                    uint32_t bd = sB + (b_col0 + nh * 32 + p * 16 + b_r) * ROWB + kb + b_kb;
                    uint32_t r[4];
                    ldmx4(r, bd);
                    bH[2 * p][0] = r[0]; bH[2 * p][1] = r[1];
                    bH[2 * p + 1][0] = r[2]; bH[2 * p + 1][1] = r[3];
                    ldmx4(r, bd + BTILE);
                    bL[2 * p][0] = r[0]; bL[2 * p][1] = r[1];
                    bL[2 * p + 1][0] = r[2]; bL[2 * p + 1][1] = r[3];
                }
                // hh batch: 16 independent accumulators
#pragma unroll
                for (int mt = 0; mt < 4; mt++)
#pragma unroll
                    for (int q = 0; q < 4; q++)
                        mma16816(acc[mt][nh * 4 + q], aH[mt], bH[q]);
                // hl batch
#pragma unroll
                for (int mt = 0; mt < 4; mt++)
#pragma unroll
                    for (int q = 0; q < 4; q++)
                        mma16816(acc[mt][nh * 4 + q], aH[mt], bL[q]);
                // lh batch
#pragma unroll
                for (int mt = 0; mt < 4; mt++)
#pragma unroll
                    for (int q = 0; q < 4; q++)
                        mma16816(acc[mt][nh * 4 + q], aL[mt], bH[q]);
            }
        }
    }
}

// ---------------- GEMM1: [gate|up] fused, SwiGLU epilogue -> bf16 hidden ----------------
__global__ __launch_bounds__(256, 1) void gemm1_mma() {
    extern __shared__ char smem[];
    const int m0 = blockIdx.y * BM;
    if (m0 >= g_off[NSEG]) return;
    const int h0 = blockIdx.x * 128;
    int seg = 0;
#pragma unroll
    for (int s = 1; s < NSEG; s++) if (m0 >= g_off[s]) seg = s;

    const int tid = threadIdx.x, lane = tid & 31, wid = tid >> 5;
    const int wm = wid & 1, wn = wid >> 1;

    const __nv_bfloat16* gAh = g_xhi + (size_t)m0 * DM;
    const __nv_bfloat16* gAl = g_xlo + (size_t)m0 * DM;
    const size_t wo = ((size_t)seg * HS + h0) * DM;

    float acc[4][8][4];
    gemm_mainloop(s2u(smem), gAh, gAl,
                  g_wghi + wo, g_wglo + wo, g_wuhi + wo, g_wulo + wo,
                  tid, acc);

    // stage fp32 acc to smem (cols 0-127 = gate, 128-255 = up)
    __syncthreads();
    float* S = reinterpret_cast<float*>(smem);
#pragma unroll
    for (int mt = 0; mt < 4; mt++) {
        const int r = wm * 64 + mt * 16 + (lane >> 2);
#pragma unroll
        for (int nt = 0; nt < 8; nt++) {
            const int c = wn * 64 + nt * 8 + (lane & 3) * 2;
            *reinterpret_cast<float2*>(S + (size_t)r * EPI_STRIDE + c) =
                make_float2(acc[mt][nt][0], acc[mt][nt][1]);
            *reinterpret_cast<float2*>(S + (size_t)(r + 8) * EPI_STRIDE + c) =
                make_float2(acc[mt][nt][2], acc[mt][nt][3]);
        }
    }
    __syncthreads();

    // swiglu + split to bf16 hi/lo
    const int row = tid >> 1, half = tid & 1;
    const float* Sg = S + (size_t)row * EPI_STRIDE + half * 64;
    const float* Su = Sg + 128;
    __nv_bfloat16* dh = g_hhi + (size_t)(m0 + row) * HS + h0 + half * 64;
    __nv_bfloat16* dl = g_hlo + (size_t)(m0 + row) * HS + h0 + half * 64;
#pragma unroll
    for (int j = 0; j < 16; j++) {
        float4 gv = *reinterpret_cast<const float4*>(Sg + 4 * j);
        float4 uv = *reinterpret_cast<const float4*>(Su + 4 * j);
        float h0v = (gv.x / (1.f + __expf(-gv.x))) * uv.x;
        float h1v = (gv.y / (1.f + __expf(-gv.y))) * uv.y;
        float h2v = (gv.z / (1.f + __expf(-gv.z))) * uv.z;
        float h3v = (gv.w / (1.f + __expf(-gv.w))) * uv.w;
        __nv_bfloat16 a, b, c, d, e, f, g, h;
        split2(h0v, a, b); split2(h1v, c, d); split2(h2v, e, f); split2(h3v, g, h);
        *reinterpret_cast<uint2*>(dh + 4 * j) = make_uint2(pack2(a, c), pack2(e, g));
        *reinterpret_cast<uint2*>(dl + 4 * j) = make_uint2(pack2(b, d), pack2(f, h));
    }
}

// ---------------- GEMM2: out[token] = H @ down_w[seg], scatter ----------------
__global__ __launch_bounds__(256, 1) void gemm2_mma(float* __restrict__ out) {
    extern __shared__ char smem[];
    const int m0 = blockIdx.y * BM;
    if (m0 >= g_off[NSEG]) return;
    const int n0 = blockIdx.x * BN;
    int seg = 0;
#pragma unroll
    for (int s = 1; s < NSEG; s++) if (m0 >= g_off[s]) seg = s;

    const int tid = threadIdx.x, lane = tid & 31, wid = tid >> 5;
    const int wm = wid & 1, wn = wid >> 1;

    const __nv_bfloat16* gAh = g_hhi + (size_t)m0 * HS;
    const __nv_bfloat16* gAl = g_hlo + (size_t)m0 * HS;
    const size_t wo = ((size_t)seg * DM + n0) * HS;
    const __nv_bfloat16* Bh = g_wdhi + wo;
    const __nv_bfloat16* Bl = g_wdlo + wo;

    float acc[4][8][4];
    gemm_mainloop(s2u(smem), gAh, gAl,
                  Bh, Bl, Bh + (size_t)128 * HS, Bl + (size_t)128 * HS,
                  tid, acc);

#pragma unroll
    for (int mt = 0; mt < 4; mt++) {
        const int rb = m0 + wm * 64 + mt * 16 + (lane >> 2);
        const int t0 = g_perm[rb];
        const int t1 = g_perm[rb + 8];
#pragma unroll
        for (int nt = 0; nt < 8; nt++) {
            const int c = n0 + wn * 64 + nt * 8 + (lane & 3) * 2;
            if (t0 >= 0)
                *reinterpret_cast<float2*>(out + (size_t)t0 * DM + c) =
                    make_float2(acc[mt][nt][0], acc[mt][nt][1]);
            if (t1 >= 0)
                *reinterpret_cast<float2*>(out + (size_t)t1 * DM + c) =
                    make_float2(acc[mt][nt][2], acc[mt][nt][3]);
        }
    }
}

// ---------------- entry point ----------------
extern "C" void kernel_launch(void* const* d_in, const int* in_sizes, int n_in,
                              void* d_out, int out_size)
{
    const float* x   = (const float*)d_in[0];
    const float* gw  = (const float*)d_in[1];
    const float* uw  = (const float*)d_in[2];
    const float* dw  = (const float*)d_in[3];
    const int*   idx = (const int*)d_in[4];
    float* out = (float*)d_out;

    static int smem_set = 0;
    if (!smem_set) {
        cudaFuncSetAttribute(gemm1_mma, cudaFuncAttributeMaxDynamicSharedMemorySize, SMEM_G);
        cudaFuncSetAttribute(gemm2_mma, cudaFuncAttributeMaxDynamicSharedMemorySize, SMEM_G);
        smem_set = 1;
    }

    k_prep<<<(MAX_ROWS + 255) / 256, 256>>>();
    k_detect<<<(NT / 2 + 255) / 256, 256>>>(idx);
    k_count<<<(NT + 255) / 256, 256>>>(idx);
    k_off<<<1, 32>>>();
    k_scatter<<<(NT + 255) / 256, 256>>>(idx);

    k_convw<<<dim3(32, 32, 12), dim3(32, 8)>>>(gw, uw, dw);
    k_convx<<<(MAX_ROWS * (DM / 4) + 255) / 256, 256>>>(x);

    gemm1_mma<<<dim3(HS / 128, MTILES), 256, SMEM_G>>>();
    gemm2_mma<<<dim3(DM / BN, MTILES), 256, SMEM_G>>>(out);
}

// round 9
// speedup vs baseline: 2.6093x; 1.0974x over previous
#include <cuda_runtime.h>
#include <cuda_bf16.h>
#include <math.h>
#include <stdint.h>

// ---------------- problem constants ----------------
#define NT   16384
#define DM   1024
#define HS   1024
#define NSEG 4
#define KDIM 1024

#define BM   128
#define BN   256
#define BK   64
#define NKIT (KDIM / BK)        // 16

#define MAX_ROWS (NT + NSEG * BM)   // 16896
#define MTILES   (MAX_ROWS / BM)    // 132
#define NPROD    (MTILES * 8)       // 1056 gemm1 CTAs
#define NCONS    (MTILES * 4)       // 528 gemm2 CTAs

// SMEM stage: rows of 64 bf16 = 128B data, padded to 144B (conflict-free ldmatrix)
#define ROWB     144
#define TILEA    (128 * ROWB)       // 18432
#define TILEB    (256 * ROWB)       // 36864
#define STAGEB   (2 * TILEA + 2 * TILEB)  // 110592
#define SMEM_G   (2 * STAGEB)       // 221184 (2-stage)
#define EPI_STRIDE 268

// ---------------- device scratch ----------------
__device__ int g_perm[MAX_ROWS];
__device__ int g_count[NSEG];
__device__ int g_cursor[NSEG];
__device__ int g_off[NSEG + 1];
__device__ int g_is32;
__device__ int g_done[MTILES];

__device__ __nv_bfloat16 g_xhi[(size_t)MAX_ROWS * DM];
__device__ __nv_bfloat16 g_xlo[(size_t)MAX_ROWS * DM];
__device__ __nv_bfloat16 g_hhi[(size_t)MAX_ROWS * HS];
__device__ __nv_bfloat16 g_hlo[(size_t)MAX_ROWS * HS];
__device__ __nv_bfloat16 g_wghi[(size_t)NSEG * HS * DM];
__device__ __nv_bfloat16 g_wglo[(size_t)NSEG * HS * DM];
__device__ __nv_bfloat16 g_wuhi[(size_t)NSEG * HS * DM];
__device__ __nv_bfloat16 g_wulo[(size_t)NSEG * HS * DM];
__device__ __nv_bfloat16 g_wdhi[(size_t)NSEG * DM * HS];
__device__ __nv_bfloat16 g_wdlo[(size_t)NSEG * DM * HS];

// ---------------- small helpers ----------------
__device__ __forceinline__ uint32_t s2u(const void* p) {
    return (uint32_t)__cvta_generic_to_shared(p);
}
__device__ __forceinline__ void cpa16(uint32_t dst, const void* src) {
    asm volatile("cp.async.cg.shared.global [%0], [%1], 16;" :: "r"(dst), "l"(src));
}
#define CP_COMMIT() asm volatile("cp.async.commit_group;" ::: "memory")
#define CP_WAIT0()  asm volatile("cp.async.wait_group 0;" ::: "memory")

__device__ __forceinline__ void ldmx4(uint32_t* r, uint32_t addr) {
    asm volatile("ldmatrix.sync.aligned.m8n8.x4.shared.b16 {%0,%1,%2,%3}, [%4];"
        : "=r"(r[0]), "=r"(r[1]), "=r"(r[2]), "=r"(r[3]) : "r"(addr));
}
__device__ __forceinline__ void mma16816(float* c, const uint32_t* a, const uint32_t* b) {
    asm volatile(
        "mma.sync.aligned.m16n8k16.row.col.f32.bf16.bf16.f32 "
        "{%0,%1,%2,%3}, {%4,%5,%6,%7}, {%8,%9}, {%0,%1,%2,%3};"
        : "+f"(c[0]), "+f"(c[1]), "+f"(c[2]), "+f"(c[3])
        : "r"(a[0]), "r"(a[1]), "r"(a[2]), "r"(a[3]), "r"(b[0]), "r"(b[1]));
}

__device__ __forceinline__ void split2(float v, __nv_bfloat16& h, __nv_bfloat16& l) {
    h = __float2bfloat16(v);
    l = __float2bfloat16(v - __bfloat162float(h));
}
__device__ __forceinline__ uint32_t pack2(__nv_bfloat16 a, __nv_bfloat16 b) {
    return ((uint32_t)__bfloat16_as_ushort(b) << 16) | __bfloat16_as_ushort(a);
}

// ---------------- routing kernels ----------------
__global__ void k_prep() {
    int i = blockIdx.x * blockDim.x + threadIdx.x;
    if (i < MAX_ROWS) g_perm[i] = -1;
    if (i < NSEG) { g_count[i] = 0; g_cursor[i] = 0; }
    if (i < MTILES) g_done[i] = 0;
    if (i == 0) g_is32 = 0;
}
__global__ void k_detect(const int* __restrict__ idx32) {
    int i = blockIdx.x * blockDim.x + threadIdx.x;
    if (i < NT / 2 && idx32[2 * i + 1] != 0) atomicExch(&g_is32, 1);
}
__device__ __forceinline__ int seg_of(const int* __restrict__ idx32, int i) {
    return (g_is32 ? idx32[i] : idx32[2 * i]) & (NSEG - 1);
}
__global__ void k_count(const int* __restrict__ idx32) {
    int i = blockIdx.x * blockDim.x + threadIdx.x;
    if (i < NT) atomicAdd(&g_count[seg_of(idx32, i)], 1);
}
__global__ void k_off() {
    if (threadIdx.x == 0 && blockIdx.x == 0) {
        int o = 0;
        for (int s = 0; s < NSEG; s++) {
            g_off[s] = o;
            o += ((g_count[s] + BM - 1) / BM) * BM;
        }
        g_off[NSEG] = o;
    }
}
__global__ void k_scatter(const int* __restrict__ idx32) {
    int i = blockIdx.x * blockDim.x + threadIdx.x;
    if (i < NT) {
        int s = seg_of(idx32, i);
        g_perm[g_off[s] + atomicAdd(&g_cursor[s], 1)] = i;
    }
}

// ---------------- conversion: gathered x -> bf16 hi/lo ----------------
__global__ void k_convx(const float* __restrict__ x) {
    int gid = blockIdx.x * blockDim.x + threadIdx.x;
    if (gid >= MAX_ROWS * (DM / 4)) return;
    int r = gid >> 8;
    int c = (gid & 255) << 2;
    int t = g_perm[r];
    float4 v = (t >= 0) ? *reinterpret_cast<const float4*>(x + (size_t)t * DM + c)
                        : make_float4(0.f, 0.f, 0.f, 0.f);
    __nv_bfloat16 hx, lx, hy, ly, hz, lz, hw, lw;
    split2(v.x, hx, lx); split2(v.y, hy, ly);
    split2(v.z, hz, lz); split2(v.w, hw, lw);
    size_t o = (size_t)r * DM + c;
    *reinterpret_cast<uint2*>(g_xhi + o) = make_uint2(pack2(hx, hy), pack2(hz, hw));
    *reinterpret_cast<uint2*>(g_xlo + o) = make_uint2(pack2(lx, ly), pack2(lz, lw));
}

// ---------------- conversion: weights fp32 [k][n] -> bf16 hi/lo [n][k] ----------------
__global__ void k_convw(const float* __restrict__ gw, const float* __restrict__ uw,
                        const float* __restrict__ dw) {
    __shared__ float tile[32][33];
    int mat = blockIdx.z >> 2, seg = blockIdx.z & 3;
    const float* W = (mat == 0 ? gw : (mat == 1 ? uw : dw)) + (size_t)seg * DM * HS;
    __nv_bfloat16* Ohi = (mat == 0 ? g_wghi : (mat == 1 ? g_wuhi : g_wdhi)) + (size_t)seg * DM * HS;
    __nv_bfloat16* Olo = (mat == 0 ? g_wglo : (mat == 1 ? g_wulo : g_wdlo)) + (size_t)seg * DM * HS;
    int n0 = blockIdx.x * 32, k0 = blockIdx.y * 32;
    int tx = threadIdx.x, ty = threadIdx.y;
#pragma unroll
    for (int i = 0; i < 4; i++)
        tile[ty + 8 * i][tx] = W[(size_t)(k0 + ty + 8 * i) * 1024 + n0 + tx];
    __syncthreads();
#pragma unroll
    for (int i = 0; i < 4; i++) {
        float v = tile[tx][ty + 8 * i];
        __nv_bfloat16 h, l; split2(v, h, l);
        size_t o = (size_t)(n0 + ty + 8 * i) * 1024 + k0 + tx;
        Ohi[o] = h; Olo[o] = l;
    }
}

// ---------------- stage loader (BK=64: 8 x 16B chunks per 144B row) ----------------
__device__ __forceinline__ void ld_stage(uint32_t sb,
        const __nv_bfloat16* gAh, const __nv_bfloat16* gAl,
        const __nv_bfloat16* B0h, const __nv_bfloat16* B0l,
        const __nv_bfloat16* B1h, const __nv_bfloat16* B1l,
        int kc, int tid) {
    const int ko = kc * BK;
#pragma unroll
    for (int q = 0; q < 4; q++) {               // A: 128 rows x 8 chunks
        int id = q * 256 + tid;
        int row = id >> 3, c = id & 7;
        uint32_t d = sb + row * ROWB + c * 16;
        const size_t so = (size_t)row * KDIM + ko + c * 8;
        cpa16(d, gAh + so);
        cpa16(d + TILEA, gAl + so);
    }
#pragma unroll
    for (int q = 0; q < 8; q++) {               // B: 256 rows x 8 chunks
        int id = q * 256 + tid;
        int row = id >> 3, c = id & 7;
        const __nv_bfloat16* sh = (row < 128) ? B0h : (B1h - (size_t)128 * KDIM);
        const __nv_bfloat16* sl = (row < 128) ? B0l : (B1l - (size_t)128 * KDIM);
        uint32_t d = sb + 2 * TILEA + row * ROWB + c * 16;
        const size_t so = (size_t)row * KDIM + ko + c * 8;
        cpa16(d, sh + so);
        cpa16(d + TILEB, sl + so);
    }
}

// ---------------- GEMM mainloop: CTA 128x256, 8 warps of 64x64, 2-stage ----------------
__device__ __forceinline__ void gemm_mainloop(uint32_t sbase,
        const __nv_bfloat16* gAh, const __nv_bfloat16* gAl,
        const __nv_bfloat16* B0h, const __nv_bfloat16* B0l,
        const __nv_bfloat16* B1h, const __nv_bfloat16* B1l,
        int tid, float acc[4][8][4]) {
    const int lane = tid & 31, wid = tid >> 5;
    const int wm = wid & 1, wn = wid >> 1;

#pragma unroll
    for (int i = 0; i < 4; i++)
#pragma unroll
        for (int j = 0; j < 8; j++)
#pragma unroll
            for (int q = 0; q < 4; q++) acc[i][j][q] = 0.f;

    ld_stage(sbase, gAh, gAl, B0h, B0l, B1h, B1l, 0, tid); CP_COMMIT();

    const int a_r  = lane & 15;
    const int a_kb = (lane >> 4) << 4;
    const int b_r  = ((lane >> 4) << 3) + (lane & 7);
    const int b_kb = ((lane >> 3) & 1) << 4;
    const int a_row0 = wm * 64;
    const int b_col0 = wn * 64;

    for (int it = 0; it < NKIT; it++) {
        CP_WAIT0();
        __syncthreads();
        if (it + 1 < NKIT) {
            ld_stage(sbase + ((it + 1) & 1) * STAGEB,
                     gAh, gAl, B0h, B0l, B1h, B1l, it + 1, tid);
            CP_COMMIT();
        }
        const uint32_t sb = sbase + (it & 1) * STAGEB;
        const uint32_t sB = sb + 2 * TILEA;
#pragma unroll
        for (int ks = 0; ks < 4; ks++) {
            const int kb = ks * 32;
            uint32_t aH[4][4], aL[4][4];
#pragma unroll
            for (int mt = 0; mt < 4; mt++) {
                uint32_t ad = sb + (a_row0 + mt * 16 + a_r) * ROWB + kb + a_kb;
                ldmx4(aH[mt], ad);
                ldmx4(aL[mt], ad + TILEA);
            }
#pragma unroll
            for (int nh = 0; nh < 2; nh++) {
                uint32_t bH[4][2], bL[4][2];
#pragma unroll
                for (int p = 0; p < 2; p++) {
                    uint32_t bd = sB + (b_col0 + nh * 32 + p * 16 + b_r) * ROWB + kb + b_kb;
                    uint32_t r[4];
                    ldmx4(r, bd);
                    bH[2 * p][0] = r[0]; bH[2 * p][1] = r[1];
                    bH[2 * p + 1][0] = r[2]; bH[2 * p + 1][1] = r[3];
                    ldmx4(r, bd + TILEB);
                    bL[2 * p][0] = r[0]; bL[2 * p][1] = r[1];
                    bL[2 * p + 1][0] = r[2]; bL[2 * p + 1][1] = r[3];
                }
#pragma unroll
                for (int mt = 0; mt < 4; mt++)
#pragma unroll
                    for (int q = 0; q < 4; q++) {
                        float* c = acc[mt][nh * 4 + q];
                        mma16816(c, aH[mt], bH[q]);
                        mma16816(c, aH[mt], bL[q]);
                        mma16816(c, aL[mt], bH[q]);
                    }
            }
        }
    }
}

// ---------------- fused GEMM kernel: producers (gemm1) + consumers (gemm2) ----------------
__global__ __launch_bounds__(256, 1) void gemm_fused(float* __restrict__ out) {
    extern __shared__ char smem[];
    const int bid = blockIdx.x;
    const int tid = threadIdx.x, lane = tid & 31, wid = tid >> 5;
    const int wm = wid & 1, wn = wid >> 1;

    if (bid < NPROD) {
        // ---- producer: gemm1 [gate|up] + fused SwiGLU ----
        const int mt_idx = bid >> 3;
        const int m0 = mt_idx * BM;
        if (m0 >= g_off[NSEG]) return;
        const int h0 = (bid & 7) * 128;
        int seg = 0;
#pragma unroll
        for (int s = 1; s < NSEG; s++) if (m0 >= g_off[s]) seg = s;

        const __nv_bfloat16* gAh = g_xhi + (size_t)m0 * DM;
        const __nv_bfloat16* gAl = g_xlo + (size_t)m0 * DM;
        const size_t wo = ((size_t)seg * HS + h0) * DM;

        float acc[4][8][4];
        gemm_mainloop(s2u(smem), gAh, gAl,
                      g_wghi + wo, g_wglo + wo, g_wuhi + wo, g_wulo + wo,
                      tid, acc);

        __syncthreads();
        float* S = reinterpret_cast<float*>(smem);
#pragma unroll
        for (int mt = 0; mt < 4; mt++) {
            const int r = wm * 64 + mt * 16 + (lane >> 2);
#pragma unroll
            for (int nt = 0; nt < 8; nt++) {
                const int c = wn * 64 + nt * 8 + (lane & 3) * 2;
                *reinterpret_cast<float2*>(S + (size_t)r * EPI_STRIDE + c) =
                    make_float2(acc[mt][nt][0], acc[mt][nt][1]);
                *reinterpret_cast<float2*>(S + (size_t)(r + 8) * EPI_STRIDE + c) =
                    make_float2(acc[mt][nt][2], acc[mt][nt][3]);
            }
        }
        __syncthreads();

        const int row = tid >> 1, half = tid & 1;
        const float* Sg = S + (size_t)row * EPI_STRIDE + half * 64;
        const float* Su = Sg + 128;
        __nv_bfloat16* dh = g_hhi + (size_t)(m0 + row) * HS + h0 + half * 64;
        __nv_bfloat16* dl = g_hlo + (size_t)(m0 + row) * HS + h0 + half * 64;
#pragma unroll
        for (int j = 0; j < 16; j++) {
            float4 gv = *reinterpret_cast<const float4*>(Sg + 4 * j);
            float4 uv = *reinterpret_cast<const float4*>(Su + 4 * j);
            float h0v = (gv.x / (1.f + __expf(-gv.x))) * uv.x;
            float h1v = (gv.y / (1.f + __expf(-gv.y))) * uv.y;
            float h2v = (gv.z / (1.f + __expf(-gv.z))) * uv.z;
            float h3v = (gv.w / (1.f + __expf(-gv.w))) * uv.w;
            __nv_bfloat16 a, b, c, d, e, f, g, h;
            split2(h0v, a, b); split2(h1v, c, d); split2(h2v, e, f); split2(h3v, g, h);
            *reinterpret_cast<uint2*>(dh + 4 * j) = make_uint2(pack2(a, c), pack2(e, g));
            *reinterpret_cast<uint2*>(dl + 4 * j) = make_uint2(pack2(b, d), pack2(f, h));
        }
        // release: hidden rows of this m-tile (for this h-slice) are globally visible
        __threadfence();
        __syncthreads();
        if (tid == 0) atomicAdd(&g_done[mt_idx], 1);
    } else {
        // ---- consumer: gemm2 with scatter epilogue ----
        const int c = bid - NPROD;
        const int mt_idx = c % MTILES;
        const int m0 = mt_idx * BM;
        if (m0 >= g_off[NSEG]) return;
        const int n0 = (c / MTILES) * BN;
        int seg = 0;
#pragma unroll
        for (int s = 1; s < NSEG; s++) if (m0 >= g_off[s]) seg = s;

        // acquire: wait for all 8 h-slices of this m-tile
        if (tid == 0) {
            while (atomicAdd(&g_done[mt_idx], 0) < 8) { }
        }
        __syncthreads();
        __threadfence();

        const __nv_bfloat16* gAh = g_hhi + (size_t)m0 * HS;
        const __nv_bfloat16* gAl = g_hlo + (size_t)m0 * HS;
        const size_t wo = ((size_t)seg * DM + n0) * HS;
        const __nv_bfloat16* Bh = g_wdhi + wo;
        const __nv_bfloat16* Bl = g_wdlo + wo;

        float acc[4][8][4];
        gemm_mainloop(s2u(smem), gAh, gAl,
                      Bh, Bl, Bh + (size_t)128 * HS, Bl + (size_t)128 * HS,
                      tid, acc);

#pragma unroll
        for (int mt = 0; mt < 4; mt++) {
            const int rb = m0 + wm * 64 + mt * 16 + (lane >> 2);
            const int t0 = g_perm[rb];
            const int t1 = g_perm[rb + 8];
#pragma unroll
            for (int nt = 0; nt < 8; nt++) {
                const int cc = n0 + wn * 64 + nt * 8 + (lane & 3) * 2;
                if (t0 >= 0)
                    *reinterpret_cast<float2*>(out + (size_t)t0 * DM + cc) =
                        make_float2(acc[mt][nt][0], acc[mt][nt][1]);
                if (t1 >= 0)
                    *reinterpret_cast<float2*>(out + (size_t)t1 * DM + cc) =
                        make_float2(acc[mt][nt][2], acc[mt][nt][3]);
            }
        }
    }
}

// ---------------- entry point ----------------
extern "C" void kernel_launch(void* const* d_in, const int* in_sizes, int n_in,
                              void* d_out, int out_size)
{
    const float* x   = (const float*)d_in[0];
    const float* gw  = (const float*)d_in[1];
    const float* uw  = (const float*)d_in[2];
    const float* dw  = (const float*)d_in[3];
    const int*   idx = (const int*)d_in[4];
    float* out = (float*)d_out;

    static int smem_set = 0;
    if (!smem_set) {
        cudaFuncSetAttribute(gemm_fused, cudaFuncAttributeMaxDynamicSharedMemorySize, SMEM_G);
        smem_set = 1;
    }

    k_prep<<<(MAX_ROWS + 255) / 256, 256>>>();
    k_detect<<<(NT / 2 + 255) / 256, 256>>>(idx);
    k_count<<<(NT + 255) / 256, 256>>>(idx);
    k_off<<<1, 32>>>();
    k_scatter<<<(NT + 255) / 256, 256>>>(idx);

    k_convw<<<dim3(32, 32, 12), dim3(32, 8)>>>(gw, uw, dw);
    k_convx<<<(MAX_ROWS * (DM / 4) + 255) / 256, 256>>>(x);

    gemm_fused<<<NPROD + NCONS, 256, SMEM_G>>>(out);
}

// round 10
// speedup vs baseline: 2.6802x; 1.0272x over previous
#include <cuda_runtime.h>
#include <cuda_bf16.h>
#include <math.h>
#include <stdint.h>

// ---------------- problem constants ----------------
#define NT   16384
#define DM   1024
#define HS   1024
#define NSEG 4
#define KDIM 1024

#define BM   128
#define BN   256
#define BK   64
#define NKIT (KDIM / BK)        // 16
#define NTHR 512                // 16 warps: 4 wm x 4 wn, warp tile 32x64

#define MAX_ROWS (NT + NSEG * BM)   // 16896
#define MTILES   (MAX_ROWS / BM)    // 132
#define NPROD    (MTILES * 8)       // 1056 gemm1 CTAs
#define NCONS    (MTILES * 4)       // 528 gemm2 CTAs

// SMEM stage: rows of 64 bf16 = 128B data, padded to 144B (conflict-free ldmatrix)
#define ROWB     144
#define TILEA    (128 * ROWB)       // 18432
#define TILEB    (256 * ROWB)       // 36864
#define STAGEB   (2 * TILEA + 2 * TILEB)  // 110592
#define SMEM_G   (2 * STAGEB)       // 221184 (2-stage)
#define EPI_STRIDE 268

// ---------------- device scratch ----------------
__device__ int g_perm[MAX_ROWS];
__device__ int g_count[NSEG];
__device__ int g_cursor[NSEG];
__device__ int g_off[NSEG + 1];
__device__ int g_is32;
__device__ int g_done[MTILES];

__device__ __nv_bfloat16 g_xhi[(size_t)MAX_ROWS * DM];
__device__ __nv_bfloat16 g_xlo[(size_t)MAX_ROWS * DM];
__device__ __nv_bfloat16 g_hhi[(size_t)MAX_ROWS * HS];
__device__ __nv_bfloat16 g_hlo[(size_t)MAX_ROWS * HS];
__device__ __nv_bfloat16 g_wghi[(size_t)NSEG * HS * DM];
__device__ __nv_bfloat16 g_wglo[(size_t)NSEG * HS * DM];
__device__ __nv_bfloat16 g_wuhi[(size_t)NSEG * HS * DM];
__device__ __nv_bfloat16 g_wulo[(size_t)NSEG * HS * DM];
__device__ __nv_bfloat16 g_wdhi[(size_t)NSEG * DM * HS];
__device__ __nv_bfloat16 g_wdlo[(size_t)NSEG * DM * HS];

// ---------------- small helpers ----------------
__device__ __forceinline__ uint32_t s2u(const void* p) {
    return (uint32_t)__cvta_generic_to_shared(p);
}
__device__ __forceinline__ void cpa16(uint32_t dst, const void* src) {
    asm volatile("cp.async.cg.shared.global [%0], [%1], 16;" :: "r"(dst), "l"(src));
}
#define CP_COMMIT() asm volatile("cp.async.commit_group;" ::: "memory")
#define CP_WAIT0()  asm volatile("cp.async.wait_group 0;" ::: "memory")

__device__ __forceinline__ void ldmx4(uint32_t* r, uint32_t addr) {
    asm volatile("ldmatrix.sync.aligned.m8n8.x4.shared.b16 {%0,%1,%2,%3}, [%4];"
        : "=r"(r[0]), "=r"(r[1]), "=r"(r[2]), "=r"(r[3]) : "r"(addr));
}
__device__ __forceinline__ void mma16816(float* c, const uint32_t* a, const uint32_t* b) {
    asm volatile(
        "mma.sync.aligned.m16n8k16.row.col.f32.bf16.bf16.f32 "
        "{%0,%1,%2,%3}, {%4,%5,%6,%7}, {%8,%9}, {%0,%1,%2,%3};"
        : "+f"(c[0]), "+f"(c[1]), "+f"(c[2]), "+f"(c[3])
        : "r"(a[0]), "r"(a[1]), "r"(a[2]), "r"(a[3]), "r"(b[0]), "r"(b[1]));
}

__device__ __forceinline__ void split2(float v, __nv_bfloat16& h, __nv_bfloat16& l) {
    h = __float2bfloat16(v);
    l = __float2bfloat16(v - __bfloat162float(h));
}
__device__ __forceinline__ uint32_t pack2(__nv_bfloat16 a, __nv_bfloat16 b) {
    return ((uint32_t)__bfloat16_as_ushort(b) << 16) | __bfloat16_as_ushort(a);
}

// ---------------- routing kernels ----------------
__global__ void k_prep() {
    int i = blockIdx.x * blockDim.x + threadIdx.x;
    if (i < MAX_ROWS) g_perm[i] = -1;
    if (i < NSEG) { g_count[i] = 0; g_cursor[i] = 0; }
    if (i < MTILES) g_done[i] = 0;
    if (i == 0) g_is32 = 0;
}
__global__ void k_detect(const int* __restrict__ idx32) {
    int i = blockIdx.x * blockDim.x + threadIdx.x;
    if (i < NT / 2 && idx32[2 * i + 1] != 0) atomicExch(&g_is32, 1);
}
__device__ __forceinline__ int seg_of(const int* __restrict__ idx32, int i) {
    return (g_is32 ? idx32[i] : idx32[2 * i]) & (NSEG - 1);
}
__global__ void k_count(const int* __restrict__ idx32) {
    int i = blockIdx.x * blockDim.x + threadIdx.x;
    if (i < NT) atomicAdd(&g_count[seg_of(idx32, i)], 1);
}
__global__ void k_off() {
    if (threadIdx.x == 0 && blockIdx.x == 0) {
        int o = 0;
        for (int s = 0; s < NSEG; s++) {
            g_off[s] = o;
            o += ((g_count[s] + BM - 1) / BM) * BM;
        }
        g_off[NSEG] = o;
    }
}
__global__ void k_scatter(const int* __restrict__ idx32) {
    int i = blockIdx.x * blockDim.x + threadIdx.x;
    if (i < NT) {
        int s = seg_of(idx32, i);
        g_perm[g_off[s] + atomicAdd(&g_cursor[s], 1)] = i;
    }
}

// ---------------- conversion: gathered x -> bf16 hi/lo ----------------
__global__ void k_convx(const float* __restrict__ x) {
    int gid = blockIdx.x * blockDim.x + threadIdx.x;
    if (gid >= MAX_ROWS * (DM / 4)) return;
    int r = gid >> 8;
    int c = (gid & 255) << 2;
    int t = g_perm[r];
    float4 v = (t >= 0) ? *reinterpret_cast<const float4*>(x + (size_t)t * DM + c)
                        : make_float4(0.f, 0.f, 0.f, 0.f);
    __nv_bfloat16 hx, lx, hy, ly, hz, lz, hw, lw;
    split2(v.x, hx, lx); split2(v.y, hy, ly);
    split2(v.z, hz, lz); split2(v.w, hw, lw);
    size_t o = (size_t)r * DM + c;
    *reinterpret_cast<uint2*>(g_xhi + o) = make_uint2(pack2(hx, hy), pack2(hz, hw));
    *reinterpret_cast<uint2*>(g_xlo + o) = make_uint2(pack2(lx, ly), pack2(lz, lw));
}

// ---------------- conversion: weights fp32 [k][n] -> bf16 hi/lo [n][k] ----------------
__global__ void k_convw(const float* __restrict__ gw, const float* __restrict__ uw,
                        const float* __restrict__ dw) {
    __shared__ float tile[32][33];
    int mat = blockIdx.z >> 2, seg = blockIdx.z & 3;
    const float* W = (mat == 0 ? gw : (mat == 1 ? uw : dw)) + (size_t)seg * DM * HS;
    __nv_bfloat16* Ohi = (mat == 0 ? g_wghi : (mat == 1 ? g_wuhi : g_wdhi)) + (size_t)seg * DM * HS;
    __nv_bfloat16* Olo = (mat == 0 ? g_wglo : (mat == 1 ? g_wulo : g_wdlo)) + (size_t)seg * DM * HS;
    int n0 = blockIdx.x * 32, k0 = blockIdx.y * 32;
    int tx = threadIdx.x, ty = threadIdx.y;
#pragma unroll
    for (int i = 0; i < 4; i++)
        tile[ty + 8 * i][tx] = W[(size_t)(k0 + ty + 8 * i) * 1024 + n0 + tx];
    __syncthreads();
#pragma unroll
    for (int i = 0; i < 4; i++) {
        float v = tile[tx][ty + 8 * i];
        __nv_bfloat16 h, l; split2(v, h, l);
        size_t o = (size_t)(n0 + ty + 8 * i) * 1024 + k0 + tx;
        Ohi[o] = h; Olo[o] = l;
    }
}

// ---------------- stage loader (512 threads; 12 cp.async each) ----------------
__device__ __forceinline__ void ld_stage(uint32_t sb,
        const __nv_bfloat16* gAh, const __nv_bfloat16* gAl,
        const __nv_bfloat16* B0h, const __nv_bfloat16* B0l,
        const __nv_bfloat16* B1h, const __nv_bfloat16* B1l,
        int kc, int tid) {
    const int ko = kc * BK;
#pragma unroll
    for (int q = 0; q < 2; q++) {               // A: 128 rows x 8 chunks (hi+lo)
        int id = q * NTHR + tid;
        int row = id >> 3, c = id & 7;
        uint32_t d = sb + row * ROWB + c * 16;
        const size_t so = (size_t)row * KDIM + ko + c * 8;
        cpa16(d, gAh + so);
        cpa16(d + TILEA, gAl + so);
    }
#pragma unroll
    for (int q = 0; q < 4; q++) {               // B: 256 rows x 8 chunks (hi+lo)
        int id = q * NTHR + tid;
        int row = id >> 3, c = id & 7;
        const __nv_bfloat16* sh = (row < 128) ? B0h : (B1h - (size_t)128 * KDIM);
        const __nv_bfloat16* sl = (row < 128) ? B0l : (B1l - (size_t)128 * KDIM);
        uint32_t d = sb + 2 * TILEA + row * ROWB + c * 16;
        const size_t so = (size_t)row * KDIM + ko + c * 8;
        cpa16(d, sh + so);
        cpa16(d + TILEB, sl + so);
    }
}

// ---------------- GEMM mainloop: CTA 128x256, 16 warps of 32x64, 2-stage ----------------
__device__ __forceinline__ void gemm_mainloop(uint32_t sbase,
        const __nv_bfloat16* gAh, const __nv_bfloat16* gAl,
        const __nv_bfloat16* B0h, const __nv_bfloat16* B0l,
        const __nv_bfloat16* B1h, const __nv_bfloat16* B1l,
        int tid, float acc[2][8][4]) {
    const int lane = tid & 31, wid = tid >> 5;
    const int wm = wid & 3, wn = wid >> 2;

#pragma unroll
    for (int i = 0; i < 2; i++)
#pragma unroll
        for (int j = 0; j < 8; j++)
#pragma unroll
            for (int q = 0; q < 4; q++) acc[i][j][q] = 0.f;

    ld_stage(sbase, gAh, gAl, B0h, B0l, B1h, B1l, 0, tid); CP_COMMIT();

    const int a_r  = lane & 15;
    const int a_kb = (lane >> 4) << 4;
    const int b_r  = ((lane >> 4) << 3) + (lane & 7);
    const int b_kb = ((lane >> 3) & 1) << 4;
    const int a_row0 = wm * 32;
    const int b_col0 = wn * 64;

    for (int it = 0; it < NKIT; it++) {
        CP_WAIT0();
        __syncthreads();
        if (it + 1 < NKIT) {
            ld_stage(sbase + ((it + 1) & 1) * STAGEB,
                     gAh, gAl, B0h, B0l, B1h, B1l, it + 1, tid);
            CP_COMMIT();
        }
        const uint32_t sb = sbase + (it & 1) * STAGEB;
        const uint32_t sB = sb + 2 * TILEA;
#pragma unroll
        for (int ks = 0; ks < 4; ks++) {
            const int kb = ks * 32;
            uint32_t aH[2][4], aL[2][4];
#pragma unroll
            for (int mt = 0; mt < 2; mt++) {
                uint32_t ad = sb + (a_row0 + mt * 16 + a_r) * ROWB + kb + a_kb;
                ldmx4(aH[mt], ad);
                ldmx4(aL[mt], ad + TILEA);
            }
#pragma unroll
            for (int nh = 0; nh < 2; nh++) {
                uint32_t bH[4][2], bL[4][2];
#pragma unroll
                for (int p = 0; p < 2; p++) {
                    uint32_t bd = sB + (b_col0 + nh * 32 + p * 16 + b_r) * ROWB + kb + b_kb;
                    uint32_t r[4];
                    ldmx4(r, bd);
                    bH[2 * p][0] = r[0]; bH[2 * p][1] = r[1];
                    bH[2 * p + 1][0] = r[2]; bH[2 * p + 1][1] = r[3];
                    ldmx4(r, bd + TILEB);
                    bL[2 * p][0] = r[0]; bL[2 * p][1] = r[1];
                    bL[2 * p + 1][0] = r[2]; bL[2 * p + 1][1] = r[3];
                }
#pragma unroll
                for (int mt = 0; mt < 2; mt++)
#pragma unroll
                    for (int q = 0; q < 4; q++) {
                        float* c = acc[mt][nh * 4 + q];
                        mma16816(c, aH[mt], bH[q]);
                        mma16816(c, aH[mt], bL[q]);
                        mma16816(c, aL[mt], bH[q]);
                    }
            }
        }
    }
}

// ---------------- fused GEMM kernel: producers (gemm1) + consumers (gemm2) ----------------
__global__ __launch_bounds__(NTHR, 1) void gemm_fused(float* __restrict__ out) {
    extern __shared__ char smem[];
    const int bid = blockIdx.x;
    const int tid = threadIdx.x, lane = tid & 31, wid = tid >> 5;
    const int wm = wid & 3, wn = wid >> 2;

    if (bid < NPROD) {
        // ---- producer: gemm1 [gate|up] + fused SwiGLU ----
        const int mt_idx = bid >> 3;
        const int m0 = mt_idx * BM;
        if (m0 >= g_off[NSEG]) return;
        const int h0 = (bid & 7) * 128;
        int seg = 0;
#pragma unroll
        for (int s = 1; s < NSEG; s++) if (m0 >= g_off[s]) seg = s;

        const __nv_bfloat16* gAh = g_xhi + (size_t)m0 * DM;
        const __nv_bfloat16* gAl = g_xlo + (size_t)m0 * DM;
        const size_t wo = ((size_t)seg * HS + h0) * DM;

        float acc[2][8][4];
        gemm_mainloop(s2u(smem), gAh, gAl,
                      g_wghi + wo, g_wglo + wo, g_wuhi + wo, g_wulo + wo,
                      tid, acc);

        __syncthreads();
        float* S = reinterpret_cast<float*>(smem);
#pragma unroll
        for (int mt = 0; mt < 2; mt++) {
            const int r = wm * 32 + mt * 16 + (lane >> 2);
#pragma unroll
            for (int nt = 0; nt < 8; nt++) {
                const int c = wn * 64 + nt * 8 + (lane & 3) * 2;
                *reinterpret_cast<float2*>(S + (size_t)r * EPI_STRIDE + c) =
                    make_float2(acc[mt][nt][0], acc[mt][nt][1]);
                *reinterpret_cast<float2*>(S + (size_t)(r + 8) * EPI_STRIDE + c) =
                    make_float2(acc[mt][nt][2], acc[mt][nt][3]);
            }
        }
        __syncthreads();

        // swiglu + split: 512 threads, each handles 32 hidden cols of one row
        const int row = tid >> 2, qtr = tid & 3;
        const float* Sg = S + (size_t)row * EPI_STRIDE + qtr * 32;
        const float* Su = Sg + 128;
        __nv_bfloat16* dh = g_hhi + (size_t)(m0 + row) * HS + h0 + qtr * 32;
        __nv_bfloat16* dl = g_hlo + (size_t)(m0 + row) * HS + h0 + qtr * 32;
#pragma unroll
        for (int j = 0; j < 8; j++) {
            float4 gv = *reinterpret_cast<const float4*>(Sg + 4 * j);
            float4 uv = *reinterpret_cast<const float4*>(Su + 4 * j);
            float h0v = (gv.x / (1.f + __expf(-gv.x))) * uv.x;
            float h1v = (gv.y / (1.f + __expf(-gv.y))) * uv.y;
            float h2v = (gv.z / (1.f + __expf(-gv.z))) * uv.z;
            float h3v = (gv.w / (1.f + __expf(-gv.w))) * uv.w;
            __nv_bfloat16 a, b, c, d, e, f, g, h;
            split2(h0v, a, b); split2(h1v, c, d); split2(h2v, e, f); split2(h3v, g, h);
            *reinterpret_cast<uint2*>(dh + 4 * j) = make_uint2(pack2(a, c), pack2(e, g));
            *reinterpret_cast<uint2*>(dl + 4 * j) = make_uint2(pack2(b, d), pack2(f, h));
        }
        __threadfence();
        __syncthreads();
        if (tid == 0) atomicAdd(&g_done[mt_idx], 1);
    } else {
        // ---- consumer: gemm2 with scatter epilogue ----
        const int c = bid - NPROD;
        const int mt_idx = c % MTILES;
        const int m0 = mt_idx * BM;
        if (m0 >= g_off[NSEG]) return;
        const int n0 = (c / MTILES) * BN;
        int seg = 0;
#pragma unroll
        for (int s = 1; s < NSEG; s++) if (m0 >= g_off[s]) seg = s;

        if (tid == 0) {
            while (atomicAdd(&g_done[mt_idx], 0) < 8) { }
        }
        __syncthreads();
        __threadfence();

        const __nv_bfloat16* gAh = g_hhi + (size_t)m0 * HS;
        const __nv_bfloat16* gAl = g_hlo + (size_t)m0 * HS;
        const size_t wo = ((size_t)seg * DM + n0) * HS;
        const __nv_bfloat16* Bh = g_wdhi + wo;
        const __nv_bfloat16* Bl = g_wdlo + wo;

        float acc[2][8][4];
        gemm_mainloop(s2u(smem), gAh, gAl,
                      Bh, Bl, Bh + (size_t)128 * HS, Bl + (size_t)128 * HS,
                      tid, acc);

#pragma unroll
        for (int mt = 0; mt < 2; mt++) {
            const int rb = m0 + wm * 32 + mt * 16 + (lane >> 2);
            const int t0 = g_perm[rb];
            const int t1 = g_perm[rb + 8];
#pragma unroll
            for (int nt = 0; nt < 8; nt++) {
                const int cc = n0 + wn * 64 + nt * 8 + (lane & 3) * 2;
                if (t0 >= 0)
                    *reinterpret_cast<float2*>(out + (size_t)t0 * DM + cc) =
                        make_float2(acc[mt][nt][0], acc[mt][nt][1]);
                if (t1 >= 0)
                    *reinterpret_cast<float2*>(out + (size_t)t1 * DM + cc) =
                        make_float2(acc[mt][nt][2], acc[mt][nt][3]);
            }
        }
    }
}

// ---------------- entry point ----------------
extern "C" void kernel_launch(void* const* d_in, const int* in_sizes, int n_in,
                              void* d_out, int out_size)
{
    const float* x   = (const float*)d_in[0];
    const float* gw  = (const float*)d_in[1];
    const float* uw  = (const float*)d_in[2];
    const float* dw  = (const float*)d_in[3];
    const int*   idx = (const int*)d_in[4];
    float* out = (float*)d_out;

    static int smem_set = 0;
    if (!smem_set) {
        cudaFuncSetAttribute(gemm_fused, cudaFuncAttributeMaxDynamicSharedMemorySize, SMEM_G);
        smem_set = 1;
    }

    k_prep<<<(MAX_ROWS + 255) / 256, 256>>>();
    k_detect<<<(NT / 2 + 255) / 256, 256>>>(idx);
    k_count<<<(NT + 255) / 256, 256>>>(idx);
    k_off<<<1, 32>>>();
    k_scatter<<<(NT + 255) / 256, 256>>>(idx);

    k_convw<<<dim3(32, 32, 12), dim3(32, 8)>>>(gw, uw, dw);
    k_convx<<<(MAX_ROWS * (DM / 4) + 255) / 256, 256>>>(x);

    gemm_fused<<<NPROD + NCONS, NTHR, SMEM_G>>>(out);
}

// round 11
// speedup vs baseline: 3.6752x; 1.3713x over previous
#include <cuda_runtime.h>
#include <cuda_fp16.h>
#include <math.h>
#include <stdint.h>

// ---------------- problem constants ----------------
#define NT   16384
#define DM   1024
#define HS   1024
#define NSEG 4
#define KDIM 1024

#define BM   128
#define BN   256
#define BK   64
#define NKIT (KDIM / BK)        // 16
#define NTHR 512                // 16 warps: 4 wm x 4 wn, warp tile 32x64

#define MAX_ROWS (NT + NSEG * BM)   // 16896
#define MTILES   (MAX_ROWS / BM)    // 132
#define NPROD    (MTILES * 8)       // 1056 gemm1 CTAs
#define NCONS    (MTILES * 4)       // 528 gemm2 CTAs

// SMEM stage: rows of 64 fp16 = 128B data, padded to 144B (conflict-free ldmatrix)
// A: 1 tile (128 rows). B: hi + lo tiles (256 rows each).
#define ROWB     144
#define TILEA    (128 * ROWB)       // 18432
#define TILEB    (256 * ROWB)       // 36864
#define STAGEB   (TILEA + 2 * TILEB)  // 92160
#define SMEM_G   (2 * STAGEB)       // 184320 (2-stage)
#define EPI_STRIDE 268

// ---------------- device scratch ----------------
__device__ int g_perm[MAX_ROWS];
__device__ int g_count[NSEG];
__device__ int g_cursor[NSEG];
__device__ int g_off[NSEG + 1];
__device__ int g_is32;
__device__ int g_done[MTILES];

__device__ __half g_xh[(size_t)MAX_ROWS * DM];   // activations, fp16 (single)
__device__ __half g_hh[(size_t)MAX_ROWS * HS];   // hidden, fp16 (single)
// weights K-major [seg][n][k], split fp16 hi/lo
__device__ __half g_wghi[(size_t)NSEG * HS * DM];
__device__ __half g_wglo[(size_t)NSEG * HS * DM];
__device__ __half g_wuhi[(size_t)NSEG * HS * DM];
__device__ __half g_wulo[(size_t)NSEG * HS * DM];
__device__ __half g_wdhi[(size_t)NSEG * DM * HS];
__device__ __half g_wdlo[(size_t)NSEG * DM * HS];

// ---------------- small helpers ----------------
__device__ __forceinline__ uint32_t s2u(const void* p) {
    return (uint32_t)__cvta_generic_to_shared(p);
}
__device__ __forceinline__ void cpa16(uint32_t dst, const void* src) {
    asm volatile("cp.async.cg.shared.global [%0], [%1], 16;" :: "r"(dst), "l"(src));
}
#define CP_COMMIT() asm volatile("cp.async.commit_group;" ::: "memory")
#define CP_WAIT0()  asm volatile("cp.async.wait_group 0;" ::: "memory")

__device__ __forceinline__ void ldmx4(uint32_t* r, uint32_t addr) {
    asm volatile("ldmatrix.sync.aligned.m8n8.x4.shared.b16 {%0,%1,%2,%3}, [%4];"
        : "=r"(r[0]), "=r"(r[1]), "=r"(r[2]), "=r"(r[3]) : "r"(addr));
}
__device__ __forceinline__ void mma16816(float* c, const uint32_t* a, const uint32_t* b) {
    asm volatile(
        "mma.sync.aligned.m16n8k16.row.col.f32.f16.f16.f32 "
        "{%0,%1,%2,%3}, {%4,%5,%6,%7}, {%8,%9}, {%0,%1,%2,%3};"
        : "+f"(c[0]), "+f"(c[1]), "+f"(c[2]), "+f"(c[3])
        : "r"(a[0]), "r"(a[1]), "r"(a[2]), "r"(a[3]), "r"(b[0]), "r"(b[1]));
}

__device__ __forceinline__ void split2h(float v, __half& h, __half& l) {
    h = __float2half(v);
    l = __float2half(v - __half2float(h));
}
__device__ __forceinline__ uint32_t packh2(__half a, __half b) {
    return ((uint32_t)__half_as_ushort(b) << 16) | __half_as_ushort(a);
}

// ---------------- routing kernels ----------------
__global__ void k_prep() {
    int i = blockIdx.x * blockDim.x + threadIdx.x;
    if (i < MAX_ROWS) g_perm[i] = -1;
    if (i < NSEG) { g_count[i] = 0; g_cursor[i] = 0; }
    if (i < MTILES) g_done[i] = 0;
    if (i == 0) g_is32 = 0;
}
__global__ void k_detect(const int* __restrict__ idx32) {
    int i = blockIdx.x * blockDim.x + threadIdx.x;
    if (i < NT / 2 && idx32[2 * i + 1] != 0) atomicExch(&g_is32, 1);
}
__device__ __forceinline__ int seg_of(const int* __restrict__ idx32, int i) {
    return (g_is32 ? idx32[i] : idx32[2 * i]) & (NSEG - 1);
}
__global__ void k_count(const int* __restrict__ idx32) {
    int i = blockIdx.x * blockDim.x + threadIdx.x;
    if (i < NT) atomicAdd(&g_count[seg_of(idx32, i)], 1);
}
__global__ void k_off() {
    if (threadIdx.x == 0 && blockIdx.x == 0) {
        int o = 0;
        for (int s = 0; s < NSEG; s++) {
            g_off[s] = o;
            o += ((g_count[s] + BM - 1) / BM) * BM;
        }
        g_off[NSEG] = o;
    }
}
__global__ void k_scatter(const int* __restrict__ idx32) {
    int i = blockIdx.x * blockDim.x + threadIdx.x;
    if (i < NT) {
        int s = seg_of(idx32, i);
        g_perm[g_off[s] + atomicAdd(&g_cursor[s], 1)] = i;
    }
}

// ---------------- conversion: gathered x -> fp16 ----------------
__global__ void k_convx(const float* __restrict__ x) {
    int gid = blockIdx.x * blockDim.x + threadIdx.x;
    if (gid >= MAX_ROWS * (DM / 4)) return;
    int r = gid >> 8;
    int c = (gid & 255) << 2;
    int t = g_perm[r];
    float4 v = (t >= 0) ? *reinterpret_cast<const float4*>(x + (size_t)t * DM + c)
                        : make_float4(0.f, 0.f, 0.f, 0.f);
    size_t o = (size_t)r * DM + c;
    *reinterpret_cast<uint2*>(g_xh + o) =
        make_uint2(packh2(__float2half(v.x), __float2half(v.y)),
                   packh2(__float2half(v.z), __float2half(v.w)));
}

// ---------------- conversion: weights fp32 [k][n] -> fp16 hi/lo [n][k] ----------------
__global__ void k_convw(const float* __restrict__ gw, const float* __restrict__ uw,
                        const float* __restrict__ dw) {
    __shared__ float tile[32][33];
    int mat = blockIdx.z >> 2, seg = blockIdx.z & 3;
    const float* W = (mat == 0 ? gw : (mat == 1 ? uw : dw)) + (size_t)seg * DM * HS;
    __half* Ohi = (mat == 0 ? g_wghi : (mat == 1 ? g_wuhi : g_wdhi)) + (size_t)seg * DM * HS;
    __half* Olo = (mat == 0 ? g_wglo : (mat == 1 ? g_wulo : g_wdlo)) + (size_t)seg * DM * HS;
    int n0 = blockIdx.x * 32, k0 = blockIdx.y * 32;
    int tx = threadIdx.x, ty = threadIdx.y;
#pragma unroll
    for (int i = 0; i < 4; i++)
        tile[ty + 8 * i][tx] = W[(size_t)(k0 + ty + 8 * i) * 1024 + n0 + tx];
    __syncthreads();
#pragma unroll
    for (int i = 0; i < 4; i++) {
        float v = tile[tx][ty + 8 * i];
        __half h, l; split2h(v, h, l);
        size_t o = (size_t)(n0 + ty + 8 * i) * 1024 + k0 + tx;
        Ohi[o] = h; Olo[o] = l;
    }
}

// ---------------- stage loader (512 threads; 10 cp.async each) ----------------
__device__ __forceinline__ void ld_stage(uint32_t sb,
        const __half* gA,
        const __half* B0h, const __half* B0l,
        const __half* B1h, const __half* B1l,
        int kc, int tid) {
    const int ko = kc * BK;
#pragma unroll
    for (int q = 0; q < 2; q++) {               // A: 128 rows x 8 chunks
        int id = q * NTHR + tid;
        int row = id >> 3, c = id & 7;
        cpa16(sb + row * ROWB + c * 16, gA + (size_t)row * KDIM + ko + c * 8);
    }
#pragma unroll
    for (int q = 0; q < 4; q++) {               // B: 256 rows x 8 chunks (hi+lo)
        int id = q * NTHR + tid;
        int row = id >> 3, c = id & 7;
        const __half* sh = (row < 128) ? B0h : (B1h - (size_t)128 * KDIM);
        const __half* sl = (row < 128) ? B0l : (B1l - (size_t)128 * KDIM);
        uint32_t d = sb + TILEA + row * ROWB + c * 16;
        const size_t so = (size_t)row * KDIM + ko + c * 8;
        cpa16(d, sh + so);
        cpa16(d + TILEB, sl + so);
    }
}

// ---------------- GEMM mainloop: CTA 128x256, 16 warps of 32x64, 2-stage ----------------
// 2-product fp16 emulation: acc += aH*bH + aH*bL  (weights split, activations single)
__device__ __forceinline__ void gemm_mainloop(uint32_t sbase,
        const __half* gA,
        const __half* B0h, const __half* B0l,
        const __half* B1h, const __half* B1l,
        int tid, float acc[2][8][4]) {
    const int lane = tid & 31, wid = tid >> 5;
    const int wm = wid & 3, wn = wid >> 2;

#pragma unroll
    for (int i = 0; i < 2; i++)
#pragma unroll
        for (int j = 0; j < 8; j++)
#pragma unroll
            for (int q = 0; q < 4; q++) acc[i][j][q] = 0.f;

    ld_stage(sbase, gA, B0h, B0l, B1h, B1l, 0, tid); CP_COMMIT();

    const int a_r  = lane & 15;
    const int a_kb = (lane >> 4) << 4;
    const int b_r  = ((lane >> 4) << 3) + (lane & 7);
    const int b_kb = ((lane >> 3) & 1) << 4;
    const int a_row0 = wm * 32;
    const int b_col0 = wn * 64;

    for (int it = 0; it < NKIT; it++) {
        CP_WAIT0();
        __syncthreads();
        if (it + 1 < NKIT) {
            ld_stage(sbase + ((it + 1) & 1) * STAGEB,
                     gA, B0h, B0l, B1h, B1l, it + 1, tid);
            CP_COMMIT();
        }
        const uint32_t sb = sbase + (it & 1) * STAGEB;
        const uint32_t sB = sb + TILEA;
#pragma unroll
        for (int ks = 0; ks < 4; ks++) {
            const int kb = ks * 32;
            uint32_t aH[2][4];
#pragma unroll
            for (int mt = 0; mt < 2; mt++) {
                uint32_t ad = sb + (a_row0 + mt * 16 + a_r) * ROWB + kb + a_kb;
                ldmx4(aH[mt], ad);
            }
#pragma unroll
            for (int nh = 0; nh < 2; nh++) {
                uint32_t bH[4][2], bL[4][2];
#pragma unroll
                for (int p = 0; p < 2; p++) {
                    uint32_t bd = sB + (b_col0 + nh * 32 + p * 16 + b_r) * ROWB + kb + b_kb;
                    uint32_t r[4];
                    ldmx4(r, bd);
                    bH[2 * p][0] = r[0]; bH[2 * p][1] = r[1];
                    bH[2 * p + 1][0] = r[2]; bH[2 * p + 1][1] = r[3];
                    ldmx4(r, bd + TILEB);
                    bL[2 * p][0] = r[0]; bL[2 * p][1] = r[1];
                    bL[2 * p + 1][0] = r[2]; bL[2 * p + 1][1] = r[3];
                }
#pragma unroll
                for (int mt = 0; mt < 2; mt++)
#pragma unroll
                    for (int q = 0; q < 4; q++) {
                        float* c = acc[mt][nh * 4 + q];
                        mma16816(c, aH[mt], bH[q]);
                        mma16816(c, aH[mt], bL[q]);
                    }
            }
        }
    }
}

// ---------------- fused GEMM kernel: producers (gemm1) + consumers (gemm2) ----------------
__global__ __launch_bounds__(NTHR, 1) void gemm_fused(float* __restrict__ out) {
    extern __shared__ char smem[];
    const int bid = blockIdx.x;
    const int tid = threadIdx.x, lane = tid & 31, wid = tid >> 5;
    const int wm = wid & 3, wn = wid >> 2;

    if (bid < NPROD) {
        // ---- producer: gemm1 [gate|up] + fused SwiGLU ----
        const int mt_idx = bid >> 3;
        const int m0 = mt_idx * BM;
        if (m0 >= g_off[NSEG]) return;
        const int h0 = (bid & 7) * 128;
        int seg = 0;
#pragma unroll
        for (int s = 1; s < NSEG; s++) if (m0 >= g_off[s]) seg = s;

        const __half* gA = g_xh + (size_t)m0 * DM;
        const size_t wo = ((size_t)seg * HS + h0) * DM;

        float acc[2][8][4];
        gemm_mainloop(s2u(smem), gA,
                      g_wghi + wo, g_wglo + wo, g_wuhi + wo, g_wulo + wo,
                      tid, acc);

        __syncthreads();
        float* S = reinterpret_cast<float*>(smem);
#pragma unroll
        for (int mt = 0; mt < 2; mt++) {
            const int r = wm * 32 + mt * 16 + (lane >> 2);
#pragma unroll
            for (int nt = 0; nt < 8; nt++) {
                const int c = wn * 64 + nt * 8 + (lane & 3) * 2;
                *reinterpret_cast<float2*>(S + (size_t)r * EPI_STRIDE + c) =
                    make_float2(acc[mt][nt][0], acc[mt][nt][1]);
                *reinterpret_cast<float2*>(S + (size_t)(r + 8) * EPI_STRIDE + c) =
                    make_float2(acc[mt][nt][2], acc[mt][nt][3]);
            }
        }
        __syncthreads();

        // swiglu -> fp16 hidden: 512 threads, each 32 hidden cols of one row
        const int row = tid >> 2, qtr = tid & 3;
        const float* Sg = S + (size_t)row * EPI_STRIDE + qtr * 32;
        const float* Su = Sg + 128;
        __half* dh = g_hh + (size_t)(m0 + row) * HS + h0 + qtr * 32;
#pragma unroll
        for (int j = 0; j < 8; j++) {
            float4 gv = *reinterpret_cast<const float4*>(Sg + 4 * j);
            float4 uv = *reinterpret_cast<const float4*>(Su + 4 * j);
            float h0v = (gv.x / (1.f + __expf(-gv.x))) * uv.x;
            float h1v = (gv.y / (1.f + __expf(-gv.y))) * uv.y;
            float h2v = (gv.z / (1.f + __expf(-gv.z))) * uv.z;
            float h3v = (gv.w / (1.f + __expf(-gv.w))) * uv.w;
            *reinterpret_cast<uint2*>(dh + 4 * j) =
                make_uint2(packh2(__float2half(h0v), __float2half(h1v)),
                           packh2(__float2half(h2v), __float2half(h3v)));
        }
        __threadfence();
        __syncthreads();
        if (tid == 0) atomicAdd(&g_done[mt_idx], 1);
    } else {
        // ---- consumer: gemm2 with scatter epilogue ----
        const int c = bid - NPROD;
        const int mt_idx = c % MTILES;
        const int m0 = mt_idx * BM;
        if (m0 >= g_off[NSEG]) return;
        const int n0 = (c / MTILES) * BN;
        int seg = 0;
#pragma unroll
        for (int s = 1; s < NSEG; s++) if (m0 >= g_off[s]) seg = s;

        if (tid == 0) {
            while (atomicAdd(&g_done[mt_idx], 0) < 8) { }
        }
        __syncthreads();
        __threadfence();

        const __half* gA = g_hh + (size_t)m0 * HS;
        const size_t wo = ((size_t)seg * DM + n0) * HS;
        const __half* Bh = g_wdhi + wo;
        const __half* Bl = g_wdlo + wo;

        float acc[2][8][4];
        gemm_mainloop(s2u(smem), gA,
                      Bh, Bl, Bh + (size_t)128 * HS, Bl + (size_t)128 * HS,
                      tid, acc);

#pragma unroll
        for (int mt = 0; mt < 2; mt++) {
            const int rb = m0 + wm * 32 + mt * 16 + (lane >> 2);
            const int t0 = g_perm[rb];
            const int t1 = g_perm[rb + 8];
#pragma unroll
            for (int nt = 0; nt < 8; nt++) {
                const int cc = n0 + wn * 64 + nt * 8 + (lane & 3) * 2;
                if (t0 >= 0)
                    *reinterpret_cast<float2*>(out + (size_t)t0 * DM + cc) =
                        make_float2(acc[mt][nt][0], acc[mt][nt][1]);
                if (t1 >= 0)
                    *reinterpret_cast<float2*>(out + (size_t)t1 * DM + cc) =
                        make_float2(acc[mt][nt][2], acc[mt][nt][3]);
            }
        }
    }
}

// ---------------- entry point ----------------
extern "C" void kernel_launch(void* const* d_in, const int* in_sizes, int n_in,
                              void* d_out, int out_size)
{
    const float* x   = (const float*)d_in[0];
    const float* gw  = (const float*)d_in[1];
    const float* uw  = (const float*)d_in[2];
    const float* dw  = (const float*)d_in[3];
    const int*   idx = (const int*)d_in[4];
    float* out = (float*)d_out;

    static int smem_set = 0;
    if (!smem_set) {
        cudaFuncSetAttribute(gemm_fused, cudaFuncAttributeMaxDynamicSharedMemorySize, SMEM_G);
        smem_set = 1;
    }

    k_prep<<<(MAX_ROWS + 255) / 256, 256>>>();
    k_detect<<<(NT / 2 + 255) / 256, 256>>>(idx);
    k_count<<<(NT + 255) / 256, 256>>>(idx);
    k_off<<<1, 32>>>();
    k_scatter<<<(NT + 255) / 256, 256>>>(idx);

    k_convw<<<dim3(32, 32, 12), dim3(32, 8)>>>(gw, uw, dw);
    k_convx<<<(MAX_ROWS * (DM / 4) + 255) / 256, 256>>>(x);

    gemm_fused<<<NPROD + NCONS, NTHR, SMEM_G>>>(out);
}

// round 12
// speedup vs baseline: 5.7651x; 1.5687x over previous
#include <cuda_runtime.h>
#include <cuda_fp16.h>
#include <math.h>
#include <stdint.h>

// ---------------- problem constants ----------------
#define NT   16384
#define DM   1024
#define HS   1024
#define NSEG 4
#define KDIM 1024

#define BM   128
#define BN   256
#define BK   64
#define NKIT (KDIM / BK)        // 16
#define NTHR 512                // 16 warps: 4 wm x 4 wn, warp tile 32x64

#define MAX_ROWS (NT + NSEG * BM)   // 16896
#define MTILES   (MAX_ROWS / BM)    // 132
#define NPROD    (MTILES * 8)       // 1056 gemm1 CTAs
#define NCONS    (MTILES * 4)       // 528 gemm2 CTAs

// SMEM stage: rows of 64 fp16 = 128B data, padded to 144B (conflict-free ldmatrix)
// A: 128 rows; B: 256 rows (single fp16, no split).
#define ROWB     144
#define TILEA    (128 * ROWB)       // 18432
#define TILEB    (256 * ROWB)       // 36864
#define STAGEB   (TILEA + TILEB)    // 55296
#define NSTAGE   3
#define SMEM_G   (NSTAGE * STAGEB)  // 165888 (>= epilogue 137216)
#define EPI_STRIDE 268

// ---------------- device scratch ----------------
__device__ int g_perm[MAX_ROWS];
__device__ int g_count[NSEG];
__device__ int g_cursor[NSEG];
__device__ int g_off[NSEG + 1];
__device__ int g_is32;
__device__ int g_done[MTILES];

__device__ __half g_xh[(size_t)MAX_ROWS * DM];   // activations fp16
__device__ __half g_hh[(size_t)MAX_ROWS * HS];   // hidden fp16
// weights K-major [seg][n][k], fp16
__device__ __half g_wg[(size_t)NSEG * HS * DM];
__device__ __half g_wu[(size_t)NSEG * HS * DM];
__device__ __half g_wd[(size_t)NSEG * DM * HS];

// ---------------- small helpers ----------------
__device__ __forceinline__ uint32_t s2u(const void* p) {
    return (uint32_t)__cvta_generic_to_shared(p);
}
__device__ __forceinline__ void cpa16(uint32_t dst, const void* src) {
    asm volatile("cp.async.cg.shared.global [%0], [%1], 16;" :: "r"(dst), "l"(src));
}
#define CP_COMMIT() asm volatile("cp.async.commit_group;" ::: "memory")
#define CP_WAIT1()  asm volatile("cp.async.wait_group 1;" ::: "memory")
#define CP_WAIT0()  asm volatile("cp.async.wait_group 0;" ::: "memory")

__device__ __forceinline__ void ldmx4(uint32_t* r, uint32_t addr) {
    asm volatile("ldmatrix.sync.aligned.m8n8.x4.shared.b16 {%0,%1,%2,%3}, [%4];"
        : "=r"(r[0]), "=r"(r[1]), "=r"(r[2]), "=r"(r[3]) : "r"(addr));
}
__device__ __forceinline__ void mma16816(float* c, const uint32_t* a, const uint32_t* b) {
    asm volatile(
        "mma.sync.aligned.m16n8k16.row.col.f32.f16.f16.f32 "
        "{%0,%1,%2,%3}, {%4,%5,%6,%7}, {%8,%9}, {%0,%1,%2,%3};"
        : "+f"(c[0]), "+f"(c[1]), "+f"(c[2]), "+f"(c[3])
        : "r"(a[0]), "r"(a[1]), "r"(a[2]), "r"(a[3]), "r"(b[0]), "r"(b[1]));
}
__device__ __forceinline__ uint32_t packh2(__half a, __half b) {
    return ((uint32_t)__half_as_ushort(b) << 16) | __half_as_ushort(a);
}

// ---------------- routing kernels ----------------
__global__ void k_prep() {
    int i = blockIdx.x * blockDim.x + threadIdx.x;
    if (i < MAX_ROWS) g_perm[i] = -1;
    if (i < NSEG) { g_count[i] = 0; g_cursor[i] = 0; }
    if (i < MTILES) g_done[i] = 0;
    if (i == 0) g_is32 = 0;
}
__global__ void k_detect(const int* __restrict__ idx32) {
    int i = blockIdx.x * blockDim.x + threadIdx.x;
    if (i < NT / 2 && idx32[2 * i + 1] != 0) atomicExch(&g_is32, 1);
}
__device__ __forceinline__ int seg_of(const int* __restrict__ idx32, int i) {
    return (g_is32 ? idx32[i] : idx32[2 * i]) & (NSEG - 1);
}
__global__ void k_count(const int* __restrict__ idx32) {
    int i = blockIdx.x * blockDim.x + threadIdx.x;
    if (i < NT) atomicAdd(&g_count[seg_of(idx32, i)], 1);
}
__global__ void k_off() {
    if (threadIdx.x == 0 && blockIdx.x == 0) {
        int o = 0;
        for (int s = 0; s < NSEG; s++) {
            g_off[s] = o;
            o += ((g_count[s] + BM - 1) / BM) * BM;
        }
        g_off[NSEG] = o;
    }
}
__global__ void k_scatter(const int* __restrict__ idx32) {
    int i = blockIdx.x * blockDim.x + threadIdx.x;
    if (i < NT) {
        int s = seg_of(idx32, i);
        g_perm[g_off[s] + atomicAdd(&g_cursor[s], 1)] = i;
    }
}

// ---------------- conversion: gathered x -> fp16 ----------------
__global__ void k_convx(const float* __restrict__ x) {
    int gid = blockIdx.x * blockDim.x + threadIdx.x;
    if (gid >= MAX_ROWS * (DM / 4)) return;
    int r = gid >> 8;
    int c = (gid & 255) << 2;
    int t = g_perm[r];
    float4 v = (t >= 0) ? *reinterpret_cast<const float4*>(x + (size_t)t * DM + c)
                        : make_float4(0.f, 0.f, 0.f, 0.f);
    size_t o = (size_t)r * DM + c;
    *reinterpret_cast<uint2*>(g_xh + o) =
        make_uint2(packh2(__float2half(v.x), __float2half(v.y)),
                   packh2(__float2half(v.z), __float2half(v.w)));
}

// ---------------- conversion: weights fp32 [k][n] -> fp16 [n][k] ----------------
__global__ void k_convw(const float* __restrict__ gw, const float* __restrict__ uw,
                        const float* __restrict__ dw) {
    __shared__ float tile[32][33];
    int mat = blockIdx.z >> 2, seg = blockIdx.z & 3;
    const float* W = (mat == 0 ? gw : (mat == 1 ? uw : dw)) + (size_t)seg * DM * HS;
    __half* O = (mat == 0 ? g_wg : (mat == 1 ? g_wu : g_wd)) + (size_t)seg * DM * HS;
    int n0 = blockIdx.x * 32, k0 = blockIdx.y * 32;
    int tx = threadIdx.x, ty = threadIdx.y;
#pragma unroll
    for (int i = 0; i < 4; i++)
        tile[ty + 8 * i][tx] = W[(size_t)(k0 + ty + 8 * i) * 1024 + n0 + tx];
    __syncthreads();
#pragma unroll
    for (int i = 0; i < 4; i++) {
        float v = tile[tx][ty + 8 * i];
        O[(size_t)(n0 + ty + 8 * i) * 1024 + k0 + tx] = __float2half(v);
    }
}

// ---------------- stage loader (512 threads; 6 cp.async each) ----------------
__device__ __forceinline__ void ld_stage(uint32_t sb,
        const __half* gA, const __half* B0, const __half* B1,
        int kc, int tid) {
    const int ko = kc * BK;
#pragma unroll
    for (int q = 0; q < 2; q++) {               // A: 128 rows x 8 chunks
        int id = q * NTHR + tid;
        int row = id >> 3, c = id & 7;
        cpa16(sb + row * ROWB + c * 16, gA + (size_t)row * KDIM + ko + c * 8);
    }
#pragma unroll
    for (int q = 0; q < 4; q++) {               // B: 256 rows x 8 chunks
        int id = q * NTHR + tid;
        int row = id >> 3, c = id & 7;
        const __half* src = (row < 128) ? B0 : (B1 - (size_t)128 * KDIM);
        cpa16(sb + TILEA + row * ROWB + c * 16, src + (size_t)row * KDIM + ko + c * 8);
    }
}

// ---------------- GEMM mainloop: CTA 128x256, 16 warps of 32x64, 3-stage ----------------
__device__ __forceinline__ void gemm_mainloop(uint32_t sbase,
        const __half* gA, const __half* B0, const __half* B1,
        int tid, float acc[2][8][4]) {
    const int lane = tid & 31, wid = tid >> 5;
    const int wm = wid & 3, wn = wid >> 2;

#pragma unroll
    for (int i = 0; i < 2; i++)
#pragma unroll
        for (int j = 0; j < 8; j++)
#pragma unroll
            for (int q = 0; q < 4; q++) acc[i][j][q] = 0.f;

    ld_stage(sbase,          gA, B0, B1, 0, tid); CP_COMMIT();
    ld_stage(sbase + STAGEB, gA, B0, B1, 1, tid); CP_COMMIT();

    const int a_r  = lane & 15;
    const int a_kb = (lane >> 4) << 4;
    const int b_r  = ((lane >> 4) << 3) + (lane & 7);
    const int b_kb = ((lane >> 3) & 1) << 4;
    const int a_row0 = wm * 32;
    const int b_col0 = wn * 64;

    for (int it = 0; it < NKIT; it++) {
        if (it + 2 < NKIT) CP_WAIT1(); else CP_WAIT0();
        __syncthreads();
        if (it + 2 < NKIT) {
            ld_stage(sbase + ((it + 2) % NSTAGE) * STAGEB, gA, B0, B1, it + 2, tid);
            CP_COMMIT();
        }
        const uint32_t sb = sbase + (it % NSTAGE) * STAGEB;
        const uint32_t sB = sb + TILEA;
#pragma unroll
        for (int ks = 0; ks < 4; ks++) {
            const int kb = ks * 32;
            uint32_t aH[2][4];
#pragma unroll
            for (int mt = 0; mt < 2; mt++) {
                uint32_t ad = sb + (a_row0 + mt * 16 + a_r) * ROWB + kb + a_kb;
                ldmx4(aH[mt], ad);
            }
#pragma unroll
            for (int nh = 0; nh < 2; nh++) {
                uint32_t bH[4][2];
#pragma unroll
                for (int p = 0; p < 2; p++) {
                    uint32_t bd = sB + (b_col0 + nh * 32 + p * 16 + b_r) * ROWB + kb + b_kb;
                    uint32_t r[4];
                    ldmx4(r, bd);
                    bH[2 * p][0] = r[0]; bH[2 * p][1] = r[1];
                    bH[2 * p + 1][0] = r[2]; bH[2 * p + 1][1] = r[3];
                }
#pragma unroll
                for (int mt = 0; mt < 2; mt++)
#pragma unroll
                    for (int q = 0; q < 4; q++)
                        mma16816(acc[mt][nh * 4 + q], aH[mt], bH[q]);
            }
        }
    }
}

// ---------------- fused GEMM kernel: producers (gemm1) + consumers (gemm2) ----------------
__global__ __launch_bounds__(NTHR, 1) void gemm_fused(float* __restrict__ out) {
    extern __shared__ char smem[];
    const int bid = blockIdx.x;
    const int tid = threadIdx.x, lane = tid & 31, wid = tid >> 5;
    const int wm = wid & 3, wn = wid >> 2;

    if (bid < NPROD) {
        // ---- producer: gemm1 [gate|up] + fused SwiGLU ----
        const int mt_idx = bid >> 3;
        const int m0 = mt_idx * BM;
        if (m0 >= g_off[NSEG]) return;
        const int h0 = (bid & 7) * 128;
        int seg = 0;
#pragma unroll
        for (int s = 1; s < NSEG; s++) if (m0 >= g_off[s]) seg = s;

        const __half* gA = g_xh + (size_t)m0 * DM;
        const size_t wo = ((size_t)seg * HS + h0) * DM;

        float acc[2][8][4];
        gemm_mainloop(s2u(smem), gA, g_wg + wo, g_wu + wo, tid, acc);

        __syncthreads();
        float* S = reinterpret_cast<float*>(smem);
#pragma unroll
        for (int mt = 0; mt < 2; mt++) {
            const int r = wm * 32 + mt * 16 + (lane >> 2);
#pragma unroll
            for (int nt = 0; nt < 8; nt++) {
                const int c = wn * 64 + nt * 8 + (lane & 3) * 2;
                *reinterpret_cast<float2*>(S + (size_t)r * EPI_STRIDE + c) =
                    make_float2(acc[mt][nt][0], acc[mt][nt][1]);
                *reinterpret_cast<float2*>(S + (size_t)(r + 8) * EPI_STRIDE + c) =
                    make_float2(acc[mt][nt][2], acc[mt][nt][3]);
            }
        }
        __syncthreads();

        // swiglu -> fp16 hidden: 512 threads, each 32 hidden cols of one row
        const int row = tid >> 2, qtr = tid & 3;
        const float* Sg = S + (size_t)row * EPI_STRIDE + qtr * 32;
        const float* Su = Sg + 128;
        __half* dh = g_hh + (size_t)(m0 + row) * HS + h0 + qtr * 32;
#pragma unroll
        for (int j = 0; j < 8; j++) {
            float4 gv = *reinterpret_cast<const float4*>(Sg + 4 * j);
            float4 uv = *reinterpret_cast<const float4*>(Su + 4 * j);
            float h0v = (gv.x / (1.f + __expf(-gv.x))) * uv.x;
            float h1v = (gv.y / (1.f + __expf(-gv.y))) * uv.y;
            float h2v = (gv.z / (1.f + __expf(-gv.z))) * uv.z;
            float h3v = (gv.w / (1.f + __expf(-gv.w))) * uv.w;
            *reinterpret_cast<uint2*>(dh + 4 * j) =
                make_uint2(packh2(__float2half(h0v), __float2half(h1v)),
                           packh2(__float2half(h2v), __float2half(h3v)));
        }
        __threadfence();
        __syncthreads();
        if (tid == 0) atomicAdd(&g_done[mt_idx], 1);
    } else {
        // ---- consumer: gemm2 with scatter epilogue ----
        const int c = bid - NPROD;
        const int mt_idx = c % MTILES;
        const int m0 = mt_idx * BM;
        if (m0 >= g_off[NSEG]) return;
        const int n0 = (c / MTILES) * BN;
        int seg = 0;
#pragma unroll
        for (int s = 1; s < NSEG; s++) if (m0 >= g_off[s]) seg = s;

        if (tid == 0) {
            while (atomicAdd(&g_done[mt_idx], 0) < 8) { }
        }
        __syncthreads();
        __threadfence();

        const __half* gA = g_hh + (size_t)m0 * HS;
        const size_t wo = ((size_t)seg * DM + n0) * HS;
        const __half* B = g_wd + wo;

        float acc[2][8][4];
        gemm_mainloop(s2u(smem), gA, B, B + (size_t)128 * HS, tid, acc);

#pragma unroll
        for (int mt = 0; mt < 2; mt++) {
            const int rb = m0 + wm * 32 + mt * 16 + (lane >> 2);
            const int t0 = g_perm[rb];
            const int t1 = g_perm[rb + 8];
#pragma unroll
            for (int nt = 0; nt < 8; nt++) {
                const int cc = n0 + wn * 64 + nt * 8 + (lane & 3) * 2;
                if (t0 >= 0)
                    *reinterpret_cast<float2*>(out + (size_t)t0 * DM + cc) =
                        make_float2(acc[mt][nt][0], acc[mt][nt][1]);
                if (t1 >= 0)
                    *reinterpret_cast<float2*>(out + (size_t)t1 * DM + cc) =
                        make_float2(acc[mt][nt][2], acc[mt][nt][3]);
            }
        }
    }
}

// ---------------- entry point ----------------
extern "C" void kernel_launch(void* const* d_in, const int* in_sizes, int n_in,
                              void* d_out, int out_size)
{
    const float* x   = (const float*)d_in[0];
    const float* gw  = (const float*)d_in[1];
    const float* uw  = (const float*)d_in[2];
    const float* dw  = (const float*)d_in[3];
    const int*   idx = (const int*)d_in[4];
    float* out = (float*)d_out;

    static int smem_set = 0;
    if (!smem_set) {
        cudaFuncSetAttribute(gemm_fused, cudaFuncAttributeMaxDynamicSharedMemorySize, SMEM_G);
        smem_set = 1;
    }

    k_prep<<<(MAX_ROWS + 255) / 256, 256>>>();
    k_detect<<<(NT / 2 + 255) / 256, 256>>>(idx);
    k_count<<<(NT + 255) / 256, 256>>>(idx);
    k_off<<<1, 32>>>();
    k_scatter<<<(NT + 255) / 256, 256>>>(idx);

    k_convw<<<dim3(32, 32, 12), dim3(32, 8)>>>(gw, uw, dw);
    k_convx<<<(MAX_ROWS * (DM / 4) + 255) / 256, 256>>>(x);

    gemm_fused<<<NPROD + NCONS, NTHR, SMEM_G>>>(out);
}